// round 2
// baseline (speedup 1.0000x reference)
#include <cuda_runtime.h>
#include <cuda_bf16.h>

#define BATCH 4
#define SEQ   2048
#define DIM   2048
#define NTOK  (BATCH*SEQ)     /* 8192 */
#define RDIM  160
#define SROWS 66              /* 2 + HEAD_SIZE */
#define D2    (DIM/2)         /* 1024 pairs per row */
#define R2    (RDIM/2)        /* 80 pairs per row  */

/* ------------------------------------------------------------------ */
/* scratch (device globals: no allocation allowed)                     */
/* ------------------------------------------------------------------ */
__device__ unsigned g_xx [(size_t)NTOK * D2];   /* bf16x2: x + sx*tmx     33.5 MB */
__device__ unsigned g_w1t[RDIM * D2];           /* bf16x2: W1^T pairs      0.65 MB */
__device__ unsigned g_xxx[(size_t)NTOK * R2];   /* bf16x2: tanh(xx@W1)     2.6 MB  */
__device__ unsigned g_w2p[5 * DIM * 16];        /* bf16x2: W2 pairs        0.65 MB */

/* ------------------------------------------------------------------ */
/* helpers                                                             */
/* ------------------------------------------------------------------ */
__device__ __forceinline__ unsigned pk(float lo, float hi) {
    unsigned r;
    asm("cvt.rn.bf16x2.f32 %0, %1, %2;" : "=r"(r) : "f"(hi), "f"(lo));
    return r;
}

#define MMA16816(d, a0, a1, a2, a3, b0, b1)                                  \
    asm volatile(                                                            \
        "mma.sync.aligned.m16n8k16.row.col.f32.bf16.bf16.f32 "               \
        "{%0,%1,%2,%3}, {%4,%5,%6,%7}, {%8,%9}, {%0,%1,%2,%3};"              \
        : "+f"(d[0]), "+f"(d[1]), "+f"(d[2]), "+f"(d[3])                     \
        : "r"(a0), "r"(a1), "r"(a2), "r"(a3), "r"(b0), "r"(b1))

/* ------------------------------------------------------------------ */
/* kernel 1: xx = x + sx * time_maa_x, packed bf16 pairs               */
/* ------------------------------------------------------------------ */
__global__ void k_prep_xx(const float* __restrict__ x,
                          const float* __restrict__ state,
                          const float* __restrict__ tmx,
                          const int*   __restrict__ ip)
{
    const int D4 = DIM / 4;                       /* 512 float4 per row */
    int idx = blockIdx.x * blockDim.x + threadIdx.x;   /* over NTOK*D4 */
    if (idx >= NTOK * D4) return;
    int j   = idx & (D4 - 1);
    int r   = idx / D4;                           /* global token row  */
    int t   = r & (SEQ - 1);
    int b   = r / SEQ;
    int c   = j * 4;
    int i1  = SROWS * ip[0] + 1;

    float4 xc = *(const float4*)(x + (size_t)r * DIM + c);
    float4 xp;
    if (t == 0)
        xp = *(const float4*)(state + ((size_t)b * SROWS + i1) * DIM + c);
    else
        xp = *(const float4*)(x + (size_t)(r - 1) * DIM + c);
    float4 m = *(const float4*)(tmx + c);

    float e0 = xc.x + (xp.x - xc.x) * m.x;
    float e1 = xc.y + (xp.y - xc.y) * m.y;
    float e2 = xc.z + (xp.z - xc.z) * m.z;
    float e3 = xc.w + (xp.w - xc.w) * m.w;

    uint2 o;
    o.x = pk(e0, e1);
    o.y = pk(e2, e3);
    *(uint2*)(g_xx + (size_t)r * D2 + 2 * j) = o;
}

/* ------------------------------------------------------------------ */
/* kernel 2: pack W1^T and W2 into bf16-pair fragment layouts          */
/* ------------------------------------------------------------------ */
__global__ void k_packw(const float* __restrict__ w1,   /* [DIM,160] */
                        const float* __restrict__ w2)   /* [5,32,DIM] */
{
    int tid = blockIdx.x * blockDim.x + threadIdx.x;
    const int NW1 = RDIM * D2;                    /* 163840 */
    if (tid < NW1) {
        int n = tid / D2;
        int j = tid - n * D2;
        float lo = w1[(size_t)(2 * j)     * RDIM + n];
        float hi = w1[(size_t)(2 * j + 1) * RDIM + n];
        g_w1t[n * D2 + j] = pk(lo, hi);
    } else {
        int q = tid - NW1;
        if (q >= 5 * DIM * 16) return;
        int f   = q / (DIM * 16);
        int rem = q - f * DIM * 16;
        int d   = rem / 16;
        int j   = rem - d * 16;
        float lo = w2[((size_t)(f * 32 + 2 * j))     * DIM + d];
        float hi = w2[((size_t)(f * 32 + 2 * j + 1)) * DIM + d];
        g_w2p[((size_t)f * DIM + d) * 16 + j] = pk(lo, hi);
    }
}

/* ------------------------------------------------------------------ */
/* kernel 3: new_state output                                          */
/* ------------------------------------------------------------------ */
__global__ void k_state(const float* __restrict__ x,
                        const float* __restrict__ state,
                        const int*   __restrict__ ip,
                        float* __restrict__ out_state)
{
    int idx = blockIdx.x * blockDim.x + threadIdx.x;
    if (idx >= BATCH * SROWS * DIM) return;
    int d   = idx & (DIM - 1);
    int row = (idx / DIM) % SROWS;
    int b   = idx / (DIM * SROWS);
    int i1  = SROWS * ip[0] + 1;
    float v = (row == i1) ? x[((size_t)b * SEQ + SEQ - 1) * DIM + d]
                          : state[idx];
    out_state[idx] = v;
}

/* ------------------------------------------------------------------ */
/* kernel 4: GEMM1  xxx = tanh(xx @ W1)  via mma.sync bf16             */
/*   grid 128 CTAs x 4 warps; CTA tile M=64, full N=160, K=2048        */
/* ------------------------------------------------------------------ */
__global__ void __launch_bounds__(128, 1) k_gemm1()
{
    int warp = threadIdx.x >> 5;
    int lane = threadIdx.x & 31;
    int gid  = lane >> 2;
    int tig  = lane & 3;

    int m0   = blockIdx.x * 64 + warp * 16;
    int rowA = m0 + gid;
    int rowB = rowA + 8;
    const unsigned* A0 = g_xx + (size_t)rowA * D2;
    const unsigned* A1 = g_xx + (size_t)rowB * D2;

    float acc[20][4];
#pragma unroll
    for (int nt = 0; nt < 20; nt++)
#pragma unroll
        for (int e = 0; e < 4; e++) acc[nt][e] = 0.f;

    for (int kk = 0; kk < DIM / 16; kk++) {
        int jb = kk * 8;
        unsigned a0 = A0[jb + tig];
        unsigned a1 = A1[jb + tig];
        unsigned a2 = A0[jb + 4 + tig];
        unsigned a3 = A1[jb + 4 + tig];
#pragma unroll
        for (int nt = 0; nt < 20; nt++) {
            const unsigned* Bb = g_w1t + (nt * 8 + gid) * D2;
            unsigned b0 = Bb[jb + tig];
            unsigned b1 = Bb[jb + 4 + tig];
            MMA16816(acc[nt], a0, a1, a2, a3, b0, b1);
        }
    }

#pragma unroll
    for (int nt = 0; nt < 20; nt++) {
        g_xxx[(size_t)rowA * R2 + nt * 4 + tig] =
            pk(tanhf(acc[nt][0]), tanhf(acc[nt][1]));
        g_xxx[(size_t)rowB * R2 + nt * 4 + tig] =
            pk(tanhf(acc[nt][2]), tanhf(acc[nt][3]));
    }
}

/* ------------------------------------------------------------------ */
/* kernel 5: GEMM2 + epilogue                                          */
/*   out[b,s,f,d] = x + sx*(maa_f[d] + sum_k xxx[..,f,k]*W2[f,k,d])    */
/*   grid (128 token-tiles of 64, 32 d-tiles of 64), 4 warps           */
/* ------------------------------------------------------------------ */
__device__ __forceinline__ void epi_row(
    const float* __restrict__ x, const float* __restrict__ state,
    const float* __restrict__ maa, float* __restrict__ out,
    int r, int b, int i1, int f, int c, float a0, float a1)
{
    int t = r & (SEQ - 1);
    size_t xo = (size_t)r * DIM + c;
    float2 xc = *(const float2*)(x + xo);
    float2 xp;
    if (t == 0)
        xp = *(const float2*)(state + ((size_t)b * SROWS + i1) * DIM + c);
    else
        xp = *(const float2*)(x + xo - DIM);
    float2 mv = *(const float2*)(maa + c);
    float2 o;
    o.x = xc.x + (xp.x - xc.x) * (mv.x + a0);
    o.y = xc.y + (xp.y - xc.y) * (mv.y + a1);
    *(float2*)(out + ((size_t)r * 5 + f) * DIM + c) = o;
}

__global__ void __launch_bounds__(128, 1) k_gemm2_epi(
    const float* __restrict__ x, const float* __restrict__ state,
    const int* __restrict__ ip,
    const float* __restrict__ mk, const float* __restrict__ mw,
    const float* __restrict__ mv, const float* __restrict__ mr,
    const float* __restrict__ mg,
    float* __restrict__ out)
{
    int warp = threadIdx.x >> 5;
    int lane = threadIdx.x & 31;
    int gid  = lane >> 2;
    int tig  = lane & 3;

    int m0 = blockIdx.x * 64;
    int d0 = blockIdx.y * 64;
    int r0 = m0 + warp * 16 + gid;
    int r1 = r0 + 8;
    int b  = m0 / SEQ;
    int i1 = SROWS * ip[0] + 1;

    const float* maas[5] = {mk, mw, mv, mr, mg};

#pragma unroll
    for (int f = 0; f < 5; f++) {
        float acc[8][4];
#pragma unroll
        for (int nt = 0; nt < 8; nt++)
#pragma unroll
            for (int e = 0; e < 4; e++) acc[nt][e] = 0.f;

        const unsigned* Ab0 = g_xxx + (size_t)r0 * R2 + f * 16;
        const unsigned* Ab1 = g_xxx + (size_t)r1 * R2 + f * 16;
#pragma unroll
        for (int s = 0; s < 2; s++) {
            unsigned a0 = Ab0[s * 8 + tig];
            unsigned a1 = Ab1[s * 8 + tig];
            unsigned a2 = Ab0[s * 8 + 4 + tig];
            unsigned a3 = Ab1[s * 8 + 4 + tig];
#pragma unroll
            for (int nt = 0; nt < 8; nt++) {
                const unsigned* Bb =
                    g_w2p + ((size_t)f * DIM + (d0 + nt * 8 + gid)) * 16;
                unsigned b0 = Bb[s * 8 + tig];
                unsigned b1 = Bb[s * 8 + 4 + tig];
                MMA16816(acc[nt], a0, a1, a2, a3, b0, b1);
            }
        }

        const float* maa = maas[f];
#pragma unroll
        for (int nt = 0; nt < 8; nt++) {
            int c = d0 + nt * 8 + 2 * tig;
            epi_row(x, state, maa, out, r0, b, i1, f, c, acc[nt][0], acc[nt][1]);
            epi_row(x, state, maa, out, r1, b, i1, f, c, acc[nt][2], acc[nt][3]);
        }
    }
}

/* ------------------------------------------------------------------ */
extern "C" void kernel_launch(void* const* d_in, const int* in_sizes, int n_in,
                              void* d_out, int out_size)
{
    const float* x     = (const float*)d_in[0];
    const float* state = (const float*)d_in[1];
    const float* tmx   = (const float*)d_in[2];
    const float* w1    = (const float*)d_in[3];
    const float* w2    = (const float*)d_in[4];
    const float* mk    = (const float*)d_in[5];
    const float* mw    = (const float*)d_in[6];
    const float* mv    = (const float*)d_in[7];
    const float* mr    = (const float*)d_in[8];
    const float* mg    = (const float*)d_in[9];
    const int*   ip    = (const int*)d_in[10];

    float* out       = (float*)d_out;
    float* out_state = out + (size_t)NTOK * 5 * DIM;

    {   /* kernel 1: prep xx */
        int n = NTOK * (DIM / 4);
        k_prep_xx<<<(n + 255) / 256, 256>>>(x, state, tmx, ip);
    }
    {   /* kernel 2: pack weights */
        int n = RDIM * D2 + 5 * DIM * 16;
        k_packw<<<(n + 255) / 256, 256>>>(w1, w2);
    }
    {   /* kernel 3: new_state */
        int n = BATCH * SROWS * DIM;
        k_state<<<(n + 255) / 256, 256>>>(x, state, ip, out_state);
    }
    /* kernel 4: GEMM1 + tanh */
    k_gemm1<<<NTOK / 64, 128>>>();
    /* kernel 5: GEMM2 + epilogue */
    k_gemm2_epi<<<dim3(NTOK / 64, DIM / 64), 128>>>(
        x, state, ip, mk, mw, mv, mr, mg, out);
}

// round 8
// speedup vs baseline: 1.4583x; 1.4583x over previous
#include <cuda_runtime.h>
#include <cuda_bf16.h>

#define BATCH 4
#define SEQ   2048
#define DIM   2048
#define NTOK  (BATCH*SEQ)     /* 8192 */
#define RDIM  160
#define SROWS 66              /* 2 + HEAD_SIZE */
#define D2    (DIM/2)         /* 1024 pairs per row */
#define R2    (RDIM/2)        /* 80 pairs per row  */

/* ------------------------------------------------------------------ */
/* scratch (device globals: no allocation allowed)                     */
/* ------------------------------------------------------------------ */
__device__ unsigned g_xx [(size_t)NTOK * D2];   /* bf16x2: x + sx*tmx  */
__device__ unsigned g_w1t[RDIM * D2];           /* bf16x2: W1^T pairs  */
__device__ unsigned g_xxx[(size_t)NTOK * R2];   /* bf16x2: tanh(xx@W1) */
__device__ unsigned g_w2p[5 * DIM * 16];        /* bf16x2: W2 pairs    */

/* ------------------------------------------------------------------ */
/* helpers                                                             */
/* ------------------------------------------------------------------ */
__device__ __forceinline__ unsigned pk(float lo, float hi) {
    unsigned r;
    asm("cvt.rn.bf16x2.f32 %0, %1, %2;" : "=r"(r) : "f"(hi), "f"(lo));
    return r;
}

__device__ __forceinline__ unsigned saddr(const void* p) {
    return (unsigned)__cvta_generic_to_shared(p);
}

__device__ __forceinline__ void cpa16(unsigned dst, const void* src) {
    asm volatile("cp.async.cg.shared.global [%0], [%1], 16;\n"
                 :: "r"(dst), "l"(src));
}

#define CP_COMMIT() asm volatile("cp.async.commit_group;\n")
#define CP_WAIT0()  asm volatile("cp.async.wait_group 0;\n")
#define CP_WAIT1()  asm volatile("cp.async.wait_group 1;\n")

#define MMA16816(d, a0, a1, a2, a3, b0, b1)                                  \
    asm volatile(                                                            \
        "mma.sync.aligned.m16n8k16.row.col.f32.bf16.bf16.f32 "               \
        "{%0,%1,%2,%3}, {%4,%5,%6,%7}, {%8,%9}, {%0,%1,%2,%3};"              \
        : "+f"(d[0]), "+f"(d[1]), "+f"(d[2]), "+f"(d[3])                     \
        : "r"(a0), "r"(a1), "r"(a2), "r"(a3), "r"(b0), "r"(b1))

/* ------------------------------------------------------------------ */
/* kernel 1: xx = x + sx * time_maa_x, packed bf16 pairs               */
/* ------------------------------------------------------------------ */
__global__ void k_prep_xx(const float* __restrict__ x,
                          const float* __restrict__ state,
                          const float* __restrict__ tmx,
                          const int*   __restrict__ ip)
{
    const int D4 = DIM / 4;
    int idx = blockIdx.x * blockDim.x + threadIdx.x;
    if (idx >= NTOK * D4) return;
    int j   = idx & (D4 - 1);
    int r   = idx / D4;
    int t   = r & (SEQ - 1);
    int b   = r / SEQ;
    int c   = j * 4;
    int i1  = SROWS * ip[0] + 1;

    float4 xc = *(const float4*)(x + (size_t)r * DIM + c);
    float4 xp;
    if (t == 0)
        xp = *(const float4*)(state + ((size_t)b * SROWS + i1) * DIM + c);
    else
        xp = *(const float4*)(x + (size_t)(r - 1) * DIM + c);
    float4 m = *(const float4*)(tmx + c);

    float e0 = xc.x + (xp.x - xc.x) * m.x;
    float e1 = xc.y + (xp.y - xc.y) * m.y;
    float e2 = xc.z + (xp.z - xc.z) * m.z;
    float e3 = xc.w + (xp.w - xc.w) * m.w;

    uint2 o;
    o.x = pk(e0, e1);
    o.y = pk(e2, e3);
    *(uint2*)(g_xx + (size_t)r * D2 + 2 * j) = o;
}

/* ------------------------------------------------------------------ */
/* kernel 2: pack W1^T and W2 into bf16-pair layouts                   */
/* ------------------------------------------------------------------ */
__global__ void k_packw(const float* __restrict__ w1,   /* [DIM,160] */
                        const float* __restrict__ w2)   /* [5,32,DIM] */
{
    int tid = blockIdx.x * blockDim.x + threadIdx.x;
    const int NW1 = RDIM * D2;
    if (tid < NW1) {
        int n = tid / D2;
        int j = tid - n * D2;
        float lo = w1[(size_t)(2 * j)     * RDIM + n];
        float hi = w1[(size_t)(2 * j + 1) * RDIM + n];
        g_w1t[n * D2 + j] = pk(lo, hi);
    } else {
        int q = tid - NW1;
        if (q >= 5 * DIM * 16) return;
        int f   = q / (DIM * 16);
        int rem = q - f * DIM * 16;
        int d   = rem / 16;
        int j   = rem - d * 16;
        float lo = w2[((size_t)(f * 32 + 2 * j))     * DIM + d];
        float hi = w2[((size_t)(f * 32 + 2 * j + 1)) * DIM + d];
        g_w2p[((size_t)f * DIM + d) * 16 + j] = pk(lo, hi);
    }
}

/* ------------------------------------------------------------------ */
/* kernel 3: new_state output                                          */
/* ------------------------------------------------------------------ */
__global__ void k_state(const float* __restrict__ x,
                        const float* __restrict__ state,
                        const int*   __restrict__ ip,
                        float* __restrict__ out_state)
{
    int idx = blockIdx.x * blockDim.x + threadIdx.x;
    if (idx >= BATCH * SROWS * DIM) return;
    int d   = idx & (DIM - 1);
    int row = (idx / DIM) % SROWS;
    int b   = idx / (DIM * SROWS);
    int i1  = SROWS * ip[0] + 1;
    float v = (row == i1) ? x[((size_t)b * SEQ + SEQ - 1) * DIM + d]
                          : state[idx];
    out_state[idx] = v;
}

/* ------------------------------------------------------------------ */
/* kernel 4: GEMM1  xxx = tanh(xx @ W1)                                */
/*   grid 256 CTAs (M-tile 32), 8 warps (warp tile 16x40)              */
/*   cp.async double-buffered smem staging for A and B                 */
/* ------------------------------------------------------------------ */
#define PC   16                 /* bf16-pairs per K-chunk (K=32)  */
#define NCH  (D2 / PC)          /* 64 chunks                      */
#define BSTR 20                 /* padded smem row stride (words) */

__global__ void __launch_bounds__(256, 1) k_gemm1()
{
    __shared__ unsigned Bs[2][RDIM * BSTR];   /* 2 x 12800 B */
    __shared__ unsigned As[2][32 * BSTR];     /* 2 x  2560 B */

    int tid  = threadIdx.x;
    int warp = tid >> 5, lane = tid & 31;
    int gid  = lane >> 2, tig = lane & 3;
    int wm   = warp >> 2, wn = warp & 3;
    int m0   = blockIdx.x * 32;

    float acc[5][4];
#pragma unroll
    for (int nt = 0; nt < 5; nt++)
#pragma unroll
        for (int e = 0; e < 4; e++) acc[nt][e] = 0.f;

    /* stage chunk c into buffer buf */
#define STAGE(buf, c)                                                        \
    do {                                                                     \
        for (int idx = tid; idx < 768; idx += 256) {                         \
            if (idx < 640) {                                                 \
                int n = idx >> 2, seg = idx & 3;                             \
                cpa16(saddr(&Bs[buf][n * BSTR + seg * 4]),                   \
                      g_w1t + (size_t)n * D2 + (c) * PC + seg * 4);          \
            } else {                                                         \
                int a2 = idx - 640;                                          \
                int row = a2 >> 2, seg = a2 & 3;                             \
                cpa16(saddr(&As[buf][row * BSTR + seg * 4]),                 \
                      g_xx + (size_t)(m0 + row) * D2 + (c) * PC + seg * 4);  \
            }                                                                \
        }                                                                    \
        CP_COMMIT();                                                         \
    } while (0)

    STAGE(0, 0);

    for (int c = 0; c < NCH; c++) {
        int cur = c & 1;
        if (c + 1 < NCH) {
            STAGE(cur ^ 1, c + 1);
            CP_WAIT1();
        } else {
            CP_WAIT0();
        }
        __syncthreads();

#pragma unroll
        for (int ks = 0; ks < 2; ks++) {
            unsigned a0 = As[cur][(wm * 16 + gid)     * BSTR + ks * 8 + tig];
            unsigned a1 = As[cur][(wm * 16 + 8 + gid) * BSTR + ks * 8 + tig];
            unsigned a2 = As[cur][(wm * 16 + gid)     * BSTR + ks * 8 + 4 + tig];
            unsigned a3 = As[cur][(wm * 16 + 8 + gid) * BSTR + ks * 8 + 4 + tig];
#pragma unroll
            for (int nt = 0; nt < 5; nt++) {
                int n = wn * 40 + nt * 8 + gid;
                unsigned b0 = Bs[cur][n * BSTR + ks * 8 + tig];
                unsigned b1 = Bs[cur][n * BSTR + ks * 8 + 4 + tig];
                MMA16816(acc[nt], a0, a1, a2, a3, b0, b1);
            }
        }
        __syncthreads();
    }

    int rowA = m0 + wm * 16 + gid;
    int rowB = rowA + 8;
#pragma unroll
    for (int nt = 0; nt < 5; nt++) {
        g_xxx[(size_t)rowA * R2 + wn * 20 + nt * 4 + tig] =
            pk(tanhf(acc[nt][0]), tanhf(acc[nt][1]));
        g_xxx[(size_t)rowB * R2 + wn * 20 + nt * 4 + tig] =
            pk(tanhf(acc[nt][2]), tanhf(acc[nt][3]));
    }
#undef STAGE
}

/* ------------------------------------------------------------------ */
/* kernel 5: GEMM2 + epilogue                                          */
/*   grid (128 token-tiles of 64, 64 d-tiles of 32), 4 warps           */
/*   all 5 modes accumulated at once; x/sx read once per output pair   */
/* ------------------------------------------------------------------ */
#define W2STR 20
#define XSTR  84

__global__ void __launch_bounds__(128, 1) k_gemm2_epi(
    const float* __restrict__ x, const float* __restrict__ state,
    const int* __restrict__ ip,
    const float* __restrict__ mk, const float* __restrict__ mw,
    const float* __restrict__ mv, const float* __restrict__ mr,
    const float* __restrict__ mg,
    float* __restrict__ out)
{
    __shared__ unsigned w2s[5 * 32 * W2STR];   /* 12800 B */
    __shared__ unsigned xs[64 * XSTR];         /* 21504 B */
    __shared__ float    ms[5][32];

    int tid  = threadIdx.x;
    int warp = tid >> 5, lane = tid & 31;
    int gid  = lane >> 2, tig = lane & 3;
    int m0   = blockIdx.x * 64, d0 = blockIdx.y * 32;

    /* stage w2 tile (5x32 cols x 16 pairs) */
    for (int idx = tid; idx < 640; idx += 128) {
        int q = idx >> 2, seg = idx & 3;
        int f = q >> 5, dn = q & 31;
        cpa16(saddr(&w2s[(f * 32 + dn) * W2STR + seg * 4]),
              g_w2p + ((size_t)f * DIM + d0 + dn) * 16 + seg * 4);
    }
    /* stage xxx rows (64 x 80 pairs) */
    for (int idx = tid; idx < 1280; idx += 128) {
        int row = idx / 20, seg = idx % 20;
        cpa16(saddr(&xs[row * XSTR + seg * 4]),
              g_xxx + (size_t)(m0 + row) * R2 + seg * 4);
    }
    CP_COMMIT();
    /* stage maa slice (160 entries, 128 threads -> strided loop!) */
    for (int idx = tid; idx < 160; idx += 128) {
        int f = idx >> 5, d = idx & 31;
        const float* p = (f == 0) ? mk : (f == 1) ? mw : (f == 2) ? mv
                        : (f == 3) ? mr : mg;
        ms[f][d] = p[d0 + d];
    }
    CP_WAIT0();
    __syncthreads();

    float acc[5][4][4];
#pragma unroll
    for (int f = 0; f < 5; f++)
#pragma unroll
        for (int nt = 0; nt < 4; nt++)
#pragma unroll
            for (int e = 0; e < 4; e++) acc[f][nt][e] = 0.f;

    int rA = warp * 16 + gid;     /* local rows */
    int rB = rA + 8;

#pragma unroll
    for (int f = 0; f < 5; f++) {
#pragma unroll
        for (int s = 0; s < 2; s++) {
            unsigned a0 = xs[rA * XSTR + f * 16 + s * 8 + tig];
            unsigned a1 = xs[rB * XSTR + f * 16 + s * 8 + tig];
            unsigned a2 = xs[rA * XSTR + f * 16 + s * 8 + 4 + tig];
            unsigned a3 = xs[rB * XSTR + f * 16 + s * 8 + 4 + tig];
#pragma unroll
            for (int nt = 0; nt < 4; nt++) {
                unsigned b0 = w2s[(f * 32 + nt * 8 + gid) * W2STR + s * 8 + tig];
                unsigned b1 = w2s[(f * 32 + nt * 8 + gid) * W2STR + s * 8 + 4 + tig];
                MMA16816(acc[f][nt], a0, a1, a2, a3, b0, b1);
            }
        }
    }

    /* epilogue */
    int i1 = SROWS * ip[0] + 1;
    int b  = m0 / SEQ;
    int r0 = m0 + warp * 16 + gid;

#pragma unroll
    for (int h = 0; h < 2; h++) {
        int r = r0 + h * 8;
        int t = r & (SEQ - 1);
        const float* xrow = x + (size_t)r * DIM;
        const float* prow = (t == 0)
            ? (state + ((size_t)b * SROWS + i1) * DIM)
            : (xrow - DIM);
#pragma unroll
        for (int nt = 0; nt < 4; nt++) {
            int cc = d0 + nt * 8 + 2 * tig;
            float2 xc = *(const float2*)(xrow + cc);
            float2 xp = *(const float2*)(prow + cc);
            float s0 = xp.x - xc.x, s1 = xp.y - xc.y;
#pragma unroll
            for (int f = 0; f < 5; f++) {
                float2 mvv = *(const float2*)(&ms[f][nt * 8 + 2 * tig]);
                float2 o;
                o.x = xc.x + s0 * (mvv.x + acc[f][nt][h * 2]);
                o.y = xc.y + s1 * (mvv.y + acc[f][nt][h * 2 + 1]);
                __stcs((float2*)(out + ((size_t)r * 5 + f) * DIM + cc), o);
            }
        }
    }
}

/* ------------------------------------------------------------------ */
extern "C" void kernel_launch(void* const* d_in, const int* in_sizes, int n_in,
                              void* d_out, int out_size)
{
    const float* x     = (const float*)d_in[0];
    const float* state = (const float*)d_in[1];
    const float* tmx   = (const float*)d_in[2];
    const float* w1    = (const float*)d_in[3];
    const float* w2    = (const float*)d_in[4];
    const float* mk    = (const float*)d_in[5];
    const float* mw    = (const float*)d_in[6];
    const float* mv    = (const float*)d_in[7];
    const float* mr    = (const float*)d_in[8];
    const float* mg    = (const float*)d_in[9];
    const int*   ip    = (const int*)d_in[10];

    float* out       = (float*)d_out;
    float* out_state = out + (size_t)NTOK * 5 * DIM;

    {   /* kernel 1: prep xx */
        int n = NTOK * (DIM / 4);
        k_prep_xx<<<(n + 255) / 256, 256>>>(x, state, tmx, ip);
    }
    {   /* kernel 2: pack weights */
        int n = RDIM * D2 + 5 * DIM * 16;
        k_packw<<<(n + 255) / 256, 256>>>(w1, w2);
    }
    {   /* kernel 3: new_state */
        int n = BATCH * SROWS * DIM;
        k_state<<<(n + 255) / 256, 256>>>(x, state, ip, out_state);
    }
    /* kernel 4: GEMM1 + tanh */
    k_gemm1<<<NTOK / 32, 256>>>();
    /* kernel 5: GEMM2 + epilogue */
    k_gemm2_epi<<<dim3(NTOK / 64, DIM / 32), 128>>>(
        x, state, ip, mk, mw, mv, mr, mg, out);
}

// round 9
// speedup vs baseline: 1.6788x; 1.1512x over previous
#include <cuda_runtime.h>
#include <cuda_bf16.h>

#define BATCH 4
#define SEQ   2048
#define DIM   2048
#define NTOK  (BATCH*SEQ)     /* 8192 */
#define RDIM  160
#define SROWS 66              /* 2 + HEAD_SIZE */
#define D2    (DIM/2)         /* 1024 pairs per row */
#define R2    (RDIM/2)        /* 80 pairs per row  */

/* ------------------------------------------------------------------ */
/* scratch (device globals: no allocation allowed)                     */
/* ------------------------------------------------------------------ */
__device__ unsigned g_xx [(size_t)NTOK * D2];   /* bf16x2: x + sx*tmx  */
__device__ unsigned g_w1t[RDIM * D2];           /* bf16x2: W1^T pairs  */
__device__ unsigned g_xxx[(size_t)NTOK * R2];   /* bf16x2: tanh(xx@W1) */
__device__ unsigned g_w2p[5 * DIM * 16];        /* bf16x2: W2 pairs    */

/* ------------------------------------------------------------------ */
/* helpers                                                             */
/* ------------------------------------------------------------------ */
__device__ __forceinline__ unsigned pk(float lo, float hi) {
    unsigned r;
    asm("cvt.rn.bf16x2.f32 %0, %1, %2;" : "=r"(r) : "f"(hi), "f"(lo));
    return r;
}

__device__ __forceinline__ unsigned saddr(const void* p) {
    return (unsigned)__cvta_generic_to_shared(p);
}

__device__ __forceinline__ void cpa16(unsigned dst, const void* src) {
    asm volatile("cp.async.cg.shared.global [%0], [%1], 16;\n"
                 :: "r"(dst), "l"(src));
}

__device__ __forceinline__ void ldsm4(unsigned& r0, unsigned& r1,
                                      unsigned& r2, unsigned& r3, unsigned a) {
    asm volatile("ldmatrix.sync.aligned.m8n8.x4.shared.b16 {%0,%1,%2,%3}, [%4];"
                 : "=r"(r0), "=r"(r1), "=r"(r2), "=r"(r3) : "r"(a));
}

#define CP_COMMIT() asm volatile("cp.async.commit_group;\n")
#define CP_WAIT0()  asm volatile("cp.async.wait_group 0;\n")
#define CP_WAIT1()  asm volatile("cp.async.wait_group 1;\n")

#define MMA16816(d, a0, a1, a2, a3, b0, b1)                                  \
    asm volatile(                                                            \
        "mma.sync.aligned.m16n8k16.row.col.f32.bf16.bf16.f32 "               \
        "{%0,%1,%2,%3}, {%4,%5,%6,%7}, {%8,%9}, {%0,%1,%2,%3};"              \
        : "+f"(d[0]), "+f"(d[1]), "+f"(d[2]), "+f"(d[3])                     \
        : "r"(a0), "r"(a1), "r"(a2), "r"(a3), "r"(b0), "r"(b1))

/* ------------------------------------------------------------------ */
/* kernel 1: xx = x + sx * time_maa_x, packed bf16 pairs               */
/* ------------------------------------------------------------------ */
__global__ void k_prep_xx(const float* __restrict__ x,
                          const float* __restrict__ state,
                          const float* __restrict__ tmx,
                          const int*   __restrict__ ip)
{
    const int D4 = DIM / 4;
    int idx = blockIdx.x * blockDim.x + threadIdx.x;
    if (idx >= NTOK * D4) return;
    int j   = idx & (D4 - 1);
    int r   = idx / D4;
    int t   = r & (SEQ - 1);
    int b   = r / SEQ;
    int c   = j * 4;
    int i1  = SROWS * ip[0] + 1;

    float4 xc = *(const float4*)(x + (size_t)r * DIM + c);
    float4 xp;
    if (t == 0)
        xp = *(const float4*)(state + ((size_t)b * SROWS + i1) * DIM + c);
    else
        xp = *(const float4*)(x + (size_t)(r - 1) * DIM + c);
    float4 m = *(const float4*)(tmx + c);

    float e0 = xc.x + (xp.x - xc.x) * m.x;
    float e1 = xc.y + (xp.y - xc.y) * m.y;
    float e2 = xc.z + (xp.z - xc.z) * m.z;
    float e3 = xc.w + (xp.w - xc.w) * m.w;

    uint2 o;
    o.x = pk(e0, e1);
    o.y = pk(e2, e3);
    *(uint2*)(g_xx + (size_t)r * D2 + 2 * j) = o;
}

/* ------------------------------------------------------------------ */
/* kernel 2: pack W1^T and W2 into bf16-pair layouts                   */
/* ------------------------------------------------------------------ */
__global__ void k_packw(const float* __restrict__ w1,   /* [DIM,160] */
                        const float* __restrict__ w2)   /* [5,32,DIM] */
{
    int tid = blockIdx.x * blockDim.x + threadIdx.x;
    const int NW1 = RDIM * D2;
    if (tid < NW1) {
        int n = tid / D2;
        int j = tid - n * D2;
        float lo = w1[(size_t)(2 * j)     * RDIM + n];
        float hi = w1[(size_t)(2 * j + 1) * RDIM + n];
        g_w1t[n * D2 + j] = pk(lo, hi);
    } else {
        int q = tid - NW1;
        if (q >= 5 * DIM * 16) return;
        int f   = q / (DIM * 16);
        int rem = q - f * DIM * 16;
        int d   = rem / 16;
        int j   = rem - d * 16;
        float lo = w2[((size_t)(f * 32 + 2 * j))     * DIM + d];
        float hi = w2[((size_t)(f * 32 + 2 * j + 1)) * DIM + d];
        g_w2p[((size_t)f * DIM + d) * 16 + j] = pk(lo, hi);
    }
}

/* ------------------------------------------------------------------ */
/* kernel 3: new_state output                                          */
/* ------------------------------------------------------------------ */
__global__ void k_state(const float* __restrict__ x,
                        const float* __restrict__ state,
                        const int*   __restrict__ ip,
                        float* __restrict__ out_state)
{
    int idx = blockIdx.x * blockDim.x + threadIdx.x;
    if (idx >= BATCH * SROWS * DIM) return;
    int d   = idx & (DIM - 1);
    int row = (idx / DIM) % SROWS;
    int b   = idx / (DIM * SROWS);
    int i1  = SROWS * ip[0] + 1;
    float v = (row == i1) ? x[((size_t)b * SEQ + SEQ - 1) * DIM + d]
                          : state[idx];
    out_state[idx] = v;
}

/* ------------------------------------------------------------------ */
/* kernel 4: GEMM1  xxx = tanh(xx @ W1)                                */
/*   M-tile 64, grid 128, 8 warps (4m x 2n, warp tile 16x80)           */
/*   ldmatrix fragment loads; race-free double-buffer cp.async         */
/* ------------------------------------------------------------------ */
#define PC   16                 /* bf16-pairs per K-chunk (K=32)  */
#define NCH  (D2 / PC)          /* 64 chunks                      */
#define BSTR 20                 /* padded smem row stride (words) */

__global__ void __launch_bounds__(256) k_gemm1()
{
    __shared__ unsigned Bs[2][RDIM * BSTR];   /* 2 x 12.8 KB */
    __shared__ unsigned As[2][64 * BSTR];     /* 2 x  5.1 KB */

    int tid  = threadIdx.x;
    int warp = tid >> 5, lane = tid & 31;
    int gid  = lane >> 2, tig = lane & 3;
    int wm   = warp & 3,  wn  = warp >> 2;
    int m0   = blockIdx.x * 64;

    float acc[10][4];
#pragma unroll
    for (int nt = 0; nt < 10; nt++)
#pragma unroll
        for (int e = 0; e < 4; e++) acc[nt][e] = 0.f;

    /* ldmatrix lane address components */
    int lg = lane >> 3, lr = lane & 7;
    unsigned aOff = ((wm * 16 + ((lg & 1) << 3) + lr) * BSTR + ((lg >> 1) << 2)) * 4;
    unsigned bOff = ((wn * 80 + ((lg >> 1) << 3) + lr) * BSTR + ((lg & 1) << 2)) * 4;

#define G1_STAGE(buf, c)                                                     \
    do {                                                                     \
        for (int idx = tid; idx < 896; idx += 256) {                         \
            if (idx < 640) {                                                 \
                int n = idx >> 2, seg = idx & 3;                             \
                cpa16(saddr(&Bs[buf][n * BSTR + seg * 4]),                   \
                      g_w1t + (size_t)n * D2 + (c) * PC + seg * 4);          \
            } else {                                                         \
                int a2 = idx - 640;                                          \
                int row = a2 >> 2, seg = a2 & 3;                             \
                cpa16(saddr(&As[buf][row * BSTR + seg * 4]),                 \
                      g_xx + (size_t)(m0 + row) * D2 + (c) * PC + seg * 4);  \
            }                                                                \
        }                                                                    \
        CP_COMMIT();                                                         \
    } while (0)

    G1_STAGE(0, 0);

    for (int c = 0; c < NCH; c++) {
        int cur = c & 1;
        __syncthreads();                  /* everyone done reading buf cur^1 */
        if (c + 1 < NCH) {
            G1_STAGE(cur ^ 1, c + 1);
            CP_WAIT1();                   /* chunk c landed */
        } else {
            CP_WAIT0();
        }
        __syncthreads();                  /* chunk c visible to all warps */

        unsigned aB = saddr(As[cur]) + aOff;
        unsigned bB = saddr(Bs[cur]) + bOff;
#pragma unroll
        for (int ks = 0; ks < 2; ks++) {
            unsigned a0, a1, a2, a3;
            ldsm4(a0, a1, a2, a3, aB + ks * 32);
#pragma unroll
            for (int u = 0; u < 5; u++) {
                unsigned b0, b1, b2, b3;
                ldsm4(b0, b1, b2, b3, bB + u * (16 * BSTR * 4) + ks * 32);
                MMA16816(acc[2 * u],     a0, a1, a2, a3, b0, b1);
                MMA16816(acc[2 * u + 1], a0, a1, a2, a3, b2, b3);
            }
        }
    }

    int rowA = m0 + wm * 16 + gid;
    int rowB = rowA + 8;
#pragma unroll
    for (int nt = 0; nt < 10; nt++) {
        g_xxx[(size_t)rowA * R2 + wn * 40 + nt * 4 + tig] =
            pk(tanhf(acc[nt][0]), tanhf(acc[nt][1]));
        g_xxx[(size_t)rowB * R2 + wn * 40 + nt * 4 + tig] =
            pk(tanhf(acc[nt][2]), tanhf(acc[nt][3]));
    }
#undef G1_STAGE
}

/* ------------------------------------------------------------------ */
/* kernel 5: GEMM2 + epilogue                                          */
/*   256 thr, tile 64 tok x 64 d; grid (128, 32); 8 warps (4m x 2n)    */
/*   smem-transposed epilogue -> float4 coalesced streaming stores     */
/* ------------------------------------------------------------------ */
#define G2WS 20     /* w2s row stride (words)  */
#define G2XS 84     /* xs  row stride (words)  */
#define G2ES 72     /* es  row stride (floats) */

__global__ void __launch_bounds__(256) k_gemm2_epi(
    const float* __restrict__ x, const float* __restrict__ state,
    const int* __restrict__ ip,
    const float* __restrict__ mk, const float* __restrict__ mw,
    const float* __restrict__ mv, const float* __restrict__ mr,
    const float* __restrict__ mg,
    float* __restrict__ out)
{
    __shared__ unsigned w2s[5 * 64 * G2WS];    /* 25600 B */
    __shared__ unsigned xs[64 * G2XS];         /* 21504 B */
    float* es = (float*)w2s;                   /* overlay after MMA phase */

    int tid  = threadIdx.x;
    int warp = tid >> 5, lane = tid & 31;
    int gid  = lane >> 2, tig = lane & 3;
    int wm   = warp & 3,  wn  = warp >> 2;
    int m0   = blockIdx.x * 64, d0 = blockIdx.y * 64;

    /* stage w2 tile (5 x 64 cols x 16 pairs) + xxx rows (64 x 80 pairs) */
    for (int idx = tid; idx < 2560; idx += 256) {
        if (idx < 1280) {
            int q = idx >> 2, seg = idx & 3;
            int f = q >> 6, dn = q & 63;
            cpa16(saddr(&w2s[(f * 64 + dn) * G2WS + seg * 4]),
                  g_w2p + ((size_t)f * DIM + d0 + dn) * 16 + seg * 4);
        } else {
            int a = idx - 1280;
            int row = a / 20, seg = a % 20;
            cpa16(saddr(&xs[row * G2XS + seg * 4]),
                  g_xxx + (size_t)(m0 + row) * R2 + seg * 4);
        }
    }
    CP_COMMIT();
    CP_WAIT0();
    __syncthreads();

    float acc[5][4][4];
#pragma unroll
    for (int f = 0; f < 5; f++)
#pragma unroll
        for (int nt = 0; nt < 4; nt++)
#pragma unroll
            for (int e = 0; e < 4; e++) acc[f][nt][e] = 0.f;

    int lg = lane >> 3, lr = lane & 7;
    unsigned aBase = saddr(xs) +
        ((wm * 16 + ((lg & 1) << 3) + lr) * G2XS + ((lg >> 1) << 2)) * 4;
    unsigned bBase = saddr(w2s) +
        ((wn * 32 + ((lg >> 1) << 3) + lr) * G2WS + ((lg & 1) << 2)) * 4;

#pragma unroll
    for (int f = 0; f < 5; f++) {
#pragma unroll
        for (int s = 0; s < 2; s++) {
            unsigned a0, a1, a2, a3;
            ldsm4(a0, a1, a2, a3, aBase + (f * 16 + s * 8) * 4);
#pragma unroll
            for (int u = 0; u < 2; u++) {
                unsigned b0, b1, b2, b3;
                ldsm4(b0, b1, b2, b3,
                      bBase + ((f * 64 + u * 16) * G2WS) * 4 + s * 32);
                MMA16816(acc[f][2 * u],     a0, a1, a2, a3, b0, b1);
                MMA16816(acc[f][2 * u + 1], a0, a1, a2, a3, b2, b3);
            }
        }
    }
    __syncthreads();    /* all smem MMA reads done before es overlay */

    int i1 = SROWS * ip[0] + 1;
    int b  = m0 / SEQ;
    const float* maas[5] = {mk, mw, mv, mr, mg};

#pragma unroll
    for (int f = 0; f < 5; f++) {
        /* scatter this mode's fragments into es */
        int row0 = wm * 16 + gid;
#pragma unroll
        for (int nt = 0; nt < 4; nt++) {
            int col = wn * 32 + nt * 8 + 2 * tig;
            *(float2*)&es[row0 * G2ES + col] =
                make_float2(acc[f][nt][0], acc[f][nt][1]);
            *(float2*)&es[(row0 + 8) * G2ES + col] =
                make_float2(acc[f][nt][2], acc[f][nt][3]);
        }
        __syncthreads();

        const float* maa = maas[f];
#pragma unroll
        for (int p = 0; p < 4; p++) {
            int idx = p * 256 + tid;
            int row = idx >> 4, cq = idx & 15;
            int c   = d0 + cq * 4;
            int r   = m0 + row;
            const float* xrow = x + (size_t)r * DIM;
            int t = r & (SEQ - 1);
            const float* prow = t ? (xrow - DIM)
                                  : (state + ((size_t)b * SROWS + i1) * DIM);
            float4 xc = *(const float4*)(xrow + c);
            float4 xp = *(const float4*)(prow + c);
            float4 mm = *(const float4*)(maa + c);
            float4 ev = *(const float4*)&es[row * G2ES + cq * 4];
            float4 o;
            o.x = xc.x + (xp.x - xc.x) * (mm.x + ev.x);
            o.y = xc.y + (xp.y - xc.y) * (mm.y + ev.y);
            o.z = xc.z + (xp.z - xc.z) * (mm.z + ev.z);
            o.w = xc.w + (xp.w - xc.w) * (mm.w + ev.w);
            __stcs((float4*)(out + ((size_t)r * 5 + f) * DIM + c), o);
        }
        __syncthreads();
    }
}

/* ------------------------------------------------------------------ */
extern "C" void kernel_launch(void* const* d_in, const int* in_sizes, int n_in,
                              void* d_out, int out_size)
{
    const float* x     = (const float*)d_in[0];
    const float* state = (const float*)d_in[1];
    const float* tmx   = (const float*)d_in[2];
    const float* w1    = (const float*)d_in[3];
    const float* w2    = (const float*)d_in[4];
    const float* mk    = (const float*)d_in[5];
    const float* mw    = (const float*)d_in[6];
    const float* mv    = (const float*)d_in[7];
    const float* mr    = (const float*)d_in[8];
    const float* mg    = (const float*)d_in[9];
    const int*   ip    = (const int*)d_in[10];

    float* out       = (float*)d_out;
    float* out_state = out + (size_t)NTOK * 5 * DIM;

    {   /* kernel 1: prep xx */
        int n = NTOK * (DIM / 4);
        k_prep_xx<<<(n + 255) / 256, 256>>>(x, state, tmx, ip);
    }
    {   /* kernel 2: pack weights */
        int n = RDIM * D2 + 5 * DIM * 16;
        k_packw<<<(n + 255) / 256, 256>>>(w1, w2);
    }
    {   /* kernel 3: new_state */
        int n = BATCH * SROWS * DIM;
        k_state<<<(n + 255) / 256, 256>>>(x, state, ip, out_state);
    }
    /* kernel 4: GEMM1 + tanh */
    k_gemm1<<<NTOK / 64, 256>>>();
    /* kernel 5: GEMM2 + epilogue */
    k_gemm2_epi<<<dim3(NTOK / 64, DIM / 64), 256>>>(
        x, state, ip, mk, mw, mv, mr, mg, out);
}

// round 10
// speedup vs baseline: 1.7479x; 1.0411x over previous
#include <cuda_runtime.h>
#include <cuda_bf16.h>

#define BATCH 4
#define SEQ   2048
#define DIM   2048
#define NTOK  (BATCH*SEQ)     /* 8192 */
#define RDIM  160
#define SROWS 66              /* 2 + HEAD_SIZE */
#define D2    (DIM/2)         /* 1024 pairs per row */
#define R2    (RDIM/2)        /* 80 pairs per row  */

/* ------------------------------------------------------------------ */
/* scratch (device globals: no allocation allowed)                     */
/* ------------------------------------------------------------------ */
__device__ unsigned g_xx [(size_t)NTOK * D2];   /* bf16x2: x + sx*tmx  */
__device__ unsigned g_w1t[RDIM * D2];           /* bf16x2: W1^T pairs  */
__device__ unsigned g_xxx[(size_t)NTOK * R2];   /* bf16x2: tanh(xx@W1) */
__device__ unsigned g_w2p[5 * DIM * 16];        /* bf16x2: W2 pairs    */

/* ------------------------------------------------------------------ */
/* helpers                                                             */
/* ------------------------------------------------------------------ */
__device__ __forceinline__ unsigned pk(float lo, float hi) {
    unsigned r;
    asm("cvt.rn.bf16x2.f32 %0, %1, %2;" : "=r"(r) : "f"(hi), "f"(lo));
    return r;
}

__device__ __forceinline__ unsigned saddr(const void* p) {
    return (unsigned)__cvta_generic_to_shared(p);
}

__device__ __forceinline__ void cpa16(unsigned dst, const void* src) {
    asm volatile("cp.async.cg.shared.global [%0], [%1], 16;\n"
                 :: "r"(dst), "l"(src));
}

__device__ __forceinline__ void ldsm4(unsigned& r0, unsigned& r1,
                                      unsigned& r2, unsigned& r3, unsigned a) {
    asm volatile("ldmatrix.sync.aligned.m8n8.x4.shared.b16 {%0,%1,%2,%3}, [%4];"
                 : "=r"(r0), "=r"(r1), "=r"(r2), "=r"(r3) : "r"(a));
}

#define CP_COMMIT() asm volatile("cp.async.commit_group;\n")
#define CP_WAIT0()  asm volatile("cp.async.wait_group 0;\n")
#define CP_WAIT1()  asm volatile("cp.async.wait_group 1;\n")
#define CP_WAIT2()  asm volatile("cp.async.wait_group 2;\n")

#define MMA16816(d, a0, a1, a2, a3, b0, b1)                                  \
    asm volatile(                                                            \
        "mma.sync.aligned.m16n8k16.row.col.f32.bf16.bf16.f32 "               \
        "{%0,%1,%2,%3}, {%4,%5,%6,%7}, {%8,%9}, {%0,%1,%2,%3};"              \
        : "+f"(d[0]), "+f"(d[1]), "+f"(d[2]), "+f"(d[3])                     \
        : "r"(a0), "r"(a1), "r"(a2), "r"(a3), "r"(b0), "r"(b1))

/* ------------------------------------------------------------------ */
/* kernel 1: xx = x + sx * time_maa_x, packed bf16 pairs               */
/* ------------------------------------------------------------------ */
__global__ void k_prep_xx(const float* __restrict__ x,
                          const float* __restrict__ state,
                          const float* __restrict__ tmx,
                          const int*   __restrict__ ip)
{
    const int D4 = DIM / 4;
    int idx = blockIdx.x * blockDim.x + threadIdx.x;
    if (idx >= NTOK * D4) return;
    int j   = idx & (D4 - 1);
    int r   = idx / D4;
    int t   = r & (SEQ - 1);
    int b   = r / SEQ;
    int c   = j * 4;
    int i1  = SROWS * ip[0] + 1;

    float4 xc = *(const float4*)(x + (size_t)r * DIM + c);
    float4 xp;
    if (t == 0)
        xp = *(const float4*)(state + ((size_t)b * SROWS + i1) * DIM + c);
    else
        xp = *(const float4*)(x + (size_t)(r - 1) * DIM + c);
    float4 m = *(const float4*)(tmx + c);

    float e0 = xc.x + (xp.x - xc.x) * m.x;
    float e1 = xc.y + (xp.y - xc.y) * m.y;
    float e2 = xc.z + (xp.z - xc.z) * m.z;
    float e3 = xc.w + (xp.w - xc.w) * m.w;

    uint2 o;
    o.x = pk(e0, e1);
    o.y = pk(e2, e3);
    *(uint2*)(g_xx + (size_t)r * D2 + 2 * j) = o;
}

/* ------------------------------------------------------------------ */
/* kernel 2: pack W1^T and W2 into bf16-pair layouts                   */
/* ------------------------------------------------------------------ */
__global__ void k_packw(const float* __restrict__ w1,   /* [DIM,160] */
                        const float* __restrict__ w2)   /* [5,32,DIM] */
{
    int tid = blockIdx.x * blockDim.x + threadIdx.x;
    const int NW1 = RDIM * D2;
    if (tid < NW1) {
        int n = tid / D2;
        int j = tid - n * D2;
        float lo = w1[(size_t)(2 * j)     * RDIM + n];
        float hi = w1[(size_t)(2 * j + 1) * RDIM + n];
        g_w1t[n * D2 + j] = pk(lo, hi);
    } else {
        int q = tid - NW1;
        if (q >= 5 * DIM * 16) return;
        int f   = q / (DIM * 16);
        int rem = q - f * DIM * 16;
        int d   = rem / 16;
        int j   = rem - d * 16;
        float lo = w2[((size_t)(f * 32 + 2 * j))     * DIM + d];
        float hi = w2[((size_t)(f * 32 + 2 * j + 1)) * DIM + d];
        g_w2p[((size_t)f * DIM + d) * 16 + j] = pk(lo, hi);
    }
}

/* ------------------------------------------------------------------ */
/* kernel 3: new_state output                                          */
/* ------------------------------------------------------------------ */
__global__ void k_state(const float* __restrict__ x,
                        const float* __restrict__ state,
                        const int*   __restrict__ ip,
                        float* __restrict__ out_state)
{
    int idx = blockIdx.x * blockDim.x + threadIdx.x;
    if (idx >= BATCH * SROWS * DIM) return;
    int d   = idx & (DIM - 1);
    int row = (idx / DIM) % SROWS;
    int b   = idx / (DIM * SROWS);
    int i1  = SROWS * ip[0] + 1;
    float v = (row == i1) ? x[((size_t)b * SEQ + SEQ - 1) * DIM + d]
                          : state[idx];
    out_state[idx] = v;
}

/* ------------------------------------------------------------------ */
/* kernel 4: GEMM1  xxx = tanh(xx @ W1)                                */
/*   M-tile 64, grid 128, 8 warps (4m x 2n, warp tile 16x80)           */
/*   3-stage cp.async pipeline, K=64 super-chunks, ldmatrix frags      */
/* ------------------------------------------------------------------ */
#define PC1   32                /* bf16-pairs per chunk (K=64)    */
#define NCH1  (D2 / PC1)        /* 32 chunks                      */
#define BSTR  36                /* padded smem row stride (words) */
#define STW   ((RDIM + 64) * BSTR)   /* words per stage = 8064    */

__global__ void __launch_bounds__(256) k_gemm1()
{
    extern __shared__ unsigned sm[];   /* 3 stages x 32256 B = 94.5 KB */

    int tid  = threadIdx.x;
    int warp = tid >> 5, lane = tid & 31;
    int gid  = lane >> 2, tig = lane & 3;
    int wm   = warp & 3,  wn  = warp >> 2;
    int m0   = blockIdx.x * 64;

    float acc[10][4];
#pragma unroll
    for (int nt = 0; nt < 10; nt++)
#pragma unroll
        for (int e = 0; e < 4; e++) acc[nt][e] = 0.f;

    /* ldmatrix lane address components (within a stage) */
    int lg = lane >> 3, lr = lane & 7;
    unsigned aOff = ((RDIM + wm * 16 + ((lg & 1) << 3) + lr) * BSTR
                     + ((lg >> 1) << 2)) * 4;
    unsigned bOff = ((wn * 80 + ((lg >> 1) << 3) + lr) * BSTR
                     + ((lg & 1) << 2)) * 4;

    /* stage chunk c into stage s: B rows then A rows (8 segs each) */
#define G1_STAGE(s, c)                                                       \
    do {                                                                     \
        unsigned* Bp = sm + (s) * STW;                                       \
        unsigned* Ap = Bp + RDIM * BSTR;                                     \
        for (int idx = tid; idx < 1792; idx += 256) {                        \
            if (idx < 1280) {                                                \
                int n = idx >> 3, seg = idx & 7;                             \
                cpa16(saddr(&Bp[n * BSTR + seg * 4]),                        \
                      g_w1t + (size_t)n * D2 + (c) * PC1 + seg * 4);         \
            } else {                                                         \
                int a2 = idx - 1280;                                         \
                int row = a2 >> 3, seg = a2 & 7;                             \
                cpa16(saddr(&Ap[row * BSTR + seg * 4]),                      \
                      g_xx + (size_t)(m0 + row) * D2 + (c) * PC1 + seg * 4); \
            }                                                                \
        }                                                                    \
        CP_COMMIT();                                                         \
    } while (0)

    G1_STAGE(0, 0);
    G1_STAGE(1, 1);

    int s = 0;
    for (int c = 0; c < NCH1; c++) {
        int s2 = s + 2; if (s2 >= 3) s2 -= 3;
        if (c + 2 < NCH1) {
            G1_STAGE(s2, c + 2);
            CP_WAIT2();
        } else if (c + 1 < NCH1) {
            CP_WAIT1();
        } else {
            CP_WAIT0();
        }
        __syncthreads();                 /* chunk c visible to all warps */

        unsigned base = saddr(sm + s * STW);
        unsigned aB = base + aOff;
        unsigned bB = base + bOff;
#pragma unroll
        for (int ks = 0; ks < 4; ks++) {
            unsigned a0, a1, a2, a3;
            ldsm4(a0, a1, a2, a3, aB + ks * 32);
#pragma unroll
            for (int u = 0; u < 5; u++) {
                unsigned b0, b1, b2, b3;
                ldsm4(b0, b1, b2, b3, bB + u * (16 * BSTR * 4) + ks * 32);
                MMA16816(acc[2 * u],     a0, a1, a2, a3, b0, b1);
                MMA16816(acc[2 * u + 1], a0, a1, a2, a3, b2, b3);
            }
        }
        __syncthreads();                 /* stage s free for re-staging */
        s = s + 1; if (s >= 3) s -= 3;
    }

    int rowA = m0 + wm * 16 + gid;
    int rowB = rowA + 8;
#pragma unroll
    for (int nt = 0; nt < 10; nt++) {
        g_xxx[(size_t)rowA * R2 + wn * 40 + nt * 4 + tig] =
            pk(tanhf(acc[nt][0]), tanhf(acc[nt][1]));
        g_xxx[(size_t)rowB * R2 + wn * 40 + nt * 4 + tig] =
            pk(tanhf(acc[nt][2]), tanhf(acc[nt][3]));
    }
#undef G1_STAGE
}

/* ------------------------------------------------------------------ */
/* kernel 5: GEMM2 + epilogue                                          */
/*   256 thr, tile 64 tok x 64 d; grid (128, 32); 8 warps (4m x 2n)    */
/*   smem-transposed epilogue -> float4 coalesced streaming stores     */
/* ------------------------------------------------------------------ */
#define G2WS 20     /* w2s row stride (words)  */
#define G2XS 84     /* xs  row stride (words)  */
#define G2ES 72     /* es  row stride (floats) */

__global__ void __launch_bounds__(256) k_gemm2_epi(
    const float* __restrict__ x, const float* __restrict__ state,
    const int* __restrict__ ip,
    const float* __restrict__ mk, const float* __restrict__ mw,
    const float* __restrict__ mv, const float* __restrict__ mr,
    const float* __restrict__ mg,
    float* __restrict__ out)
{
    __shared__ unsigned w2s[5 * 64 * G2WS];    /* 25600 B */
    __shared__ unsigned xs[64 * G2XS];         /* 21504 B */
    float* es = (float*)w2s;                   /* overlay after MMA phase */

    int tid  = threadIdx.x;
    int warp = tid >> 5, lane = tid & 31;
    int gid  = lane >> 2, tig = lane & 3;
    int wm   = warp & 3,  wn  = warp >> 2;
    int m0   = blockIdx.x * 64, d0 = blockIdx.y * 64;

    /* stage w2 tile (5 x 64 cols x 16 pairs) + xxx rows (64 x 80 pairs) */
    for (int idx = tid; idx < 2560; idx += 256) {
        if (idx < 1280) {
            int q = idx >> 2, seg = idx & 3;
            int f = q >> 6, dn = q & 63;
            cpa16(saddr(&w2s[(f * 64 + dn) * G2WS + seg * 4]),
                  g_w2p + ((size_t)f * DIM + d0 + dn) * 16 + seg * 4);
        } else {
            int a = idx - 1280;
            int row = a / 20, seg = a % 20;
            cpa16(saddr(&xs[row * G2XS + seg * 4]),
                  g_xxx + (size_t)(m0 + row) * R2 + seg * 4);
        }
    }
    CP_COMMIT();
    CP_WAIT0();
    __syncthreads();

    float acc[5][4][4];
#pragma unroll
    for (int f = 0; f < 5; f++)
#pragma unroll
        for (int nt = 0; nt < 4; nt++)
#pragma unroll
            for (int e = 0; e < 4; e++) acc[f][nt][e] = 0.f;

    int lg = lane >> 3, lr = lane & 7;
    unsigned aBase = saddr(xs) +
        ((wm * 16 + ((lg & 1) << 3) + lr) * G2XS + ((lg >> 1) << 2)) * 4;
    unsigned bBase = saddr(w2s) +
        ((wn * 32 + ((lg >> 1) << 3) + lr) * G2WS + ((lg & 1) << 2)) * 4;

#pragma unroll
    for (int f = 0; f < 5; f++) {
#pragma unroll
        for (int s = 0; s < 2; s++) {
            unsigned a0, a1, a2, a3;
            ldsm4(a0, a1, a2, a3, aBase + (f * 16 + s * 8) * 4);
#pragma unroll
            for (int u = 0; u < 2; u++) {
                unsigned b0, b1, b2, b3;
                ldsm4(b0, b1, b2, b3,
                      bBase + ((f * 64 + u * 16) * G2WS) * 4 + s * 32);
                MMA16816(acc[f][2 * u],     a0, a1, a2, a3, b0, b1);
                MMA16816(acc[f][2 * u + 1], a0, a1, a2, a3, b2, b3);
            }
        }
    }
    __syncthreads();    /* all smem MMA reads done before es overlay */

    int i1 = SROWS * ip[0] + 1;
    int b  = m0 / SEQ;
    const float* maas[5] = {mk, mw, mv, mr, mg};

#pragma unroll
    for (int f = 0; f < 5; f++) {
        /* scatter this mode's fragments into es */
        int row0 = wm * 16 + gid;
#pragma unroll
        for (int nt = 0; nt < 4; nt++) {
            int col = wn * 32 + nt * 8 + 2 * tig;
            *(float2*)&es[row0 * G2ES + col] =
                make_float2(acc[f][nt][0], acc[f][nt][1]);
            *(float2*)&es[(row0 + 8) * G2ES + col] =
                make_float2(acc[f][nt][2], acc[f][nt][3]);
        }
        __syncthreads();

        const float* maa = maas[f];
#pragma unroll
        for (int p = 0; p < 4; p++) {
            int idx = p * 256 + tid;
            int row = idx >> 4, cq = idx & 15;
            int c   = d0 + cq * 4;
            int r   = m0 + row;
            const float* xrow = x + (size_t)r * DIM;
            int t = r & (SEQ - 1);
            const float* prow = t ? (xrow - DIM)
                                  : (state + ((size_t)b * SROWS + i1) * DIM);
            float4 xc = *(const float4*)(xrow + c);
            float4 xp = *(const float4*)(prow + c);
            float4 mm = *(const float4*)(maa + c);
            float4 ev = *(const float4*)&es[row * G2ES + cq * 4];
            float4 o;
            o.x = xc.x + (xp.x - xc.x) * (mm.x + ev.x);
            o.y = xc.y + (xp.y - xc.y) * (mm.y + ev.y);
            o.z = xc.z + (xp.z - xc.z) * (mm.z + ev.z);
            o.w = xc.w + (xp.w - xc.w) * (mm.w + ev.w);
            __stcs((float4*)(out + ((size_t)r * 5 + f) * DIM + c), o);
        }
        __syncthreads();
    }
}

/* ------------------------------------------------------------------ */
extern "C" void kernel_launch(void* const* d_in, const int* in_sizes, int n_in,
                              void* d_out, int out_size)
{
    const float* x     = (const float*)d_in[0];
    const float* state = (const float*)d_in[1];
    const float* tmx   = (const float*)d_in[2];
    const float* w1    = (const float*)d_in[3];
    const float* w2    = (const float*)d_in[4];
    const float* mk    = (const float*)d_in[5];
    const float* mw    = (const float*)d_in[6];
    const float* mv    = (const float*)d_in[7];
    const float* mr    = (const float*)d_in[8];
    const float* mg    = (const float*)d_in[9];
    const int*   ip    = (const int*)d_in[10];

    float* out       = (float*)d_out;
    float* out_state = out + (size_t)NTOK * 5 * DIM;

    static int smem_set = 0;
    const int g1_smem = 3 * STW * 4;   /* 96768 B */
    if (!smem_set) {
        cudaFuncSetAttribute(k_gemm1,
            cudaFuncAttributeMaxDynamicSharedMemorySize, g1_smem);
        smem_set = 1;
    }

    {   /* kernel 1: prep xx */
        int n = NTOK * (DIM / 4);
        k_prep_xx<<<(n + 255) / 256, 256>>>(x, state, tmx, ip);
    }
    {   /* kernel 2: pack weights */
        int n = RDIM * D2 + 5 * DIM * 16;
        k_packw<<<(n + 255) / 256, 256>>>(w1, w2);
    }
    {   /* kernel 3: new_state */
        int n = BATCH * SROWS * DIM;
        k_state<<<(n + 255) / 256, 256>>>(x, state, ip, out_state);
    }
    /* kernel 4: GEMM1 + tanh */
    k_gemm1<<<NTOK / 64, 256, g1_smem>>>();
    /* kernel 5: GEMM2 + epilogue */
    k_gemm2_epi<<<dim3(NTOK / 64, DIM / 64), 256>>>(
        x, state, ip, mk, mw, mv, mr, mg, out);
}

// round 14
// speedup vs baseline: 1.8177x; 1.0400x over previous
#include <cuda_runtime.h>
#include <cuda_bf16.h>

#define BATCH 4
#define SEQ   2048
#define DIM   2048
#define NTOK  (BATCH*SEQ)     /* 8192 */
#define RDIM  160
#define SROWS 66              /* 2 + HEAD_SIZE */
#define D2    (DIM/2)         /* 1024 pairs per row */
#define R2    (RDIM/2)        /* 80 pairs per row  */

/* ------------------------------------------------------------------ */
/* scratch (device globals: no allocation allowed)                     */
/* ------------------------------------------------------------------ */
__device__ unsigned g_xx [(size_t)NTOK * D2];   /* bf16x2: x + sx*tmx  */
__device__ unsigned g_w1t[RDIM * D2];           /* bf16x2: W1^T pairs  */
__device__ unsigned g_xxx[(size_t)NTOK * R2];   /* bf16x2: tanh(xx@W1) */
__device__ unsigned g_w2p[5 * DIM * 16];        /* bf16x2: W2 pairs    */
__device__ float2   g_p1[2][(size_t)NTOK * R2]; /* fp32 split-K partials */

/* ------------------------------------------------------------------ */
/* helpers                                                             */
/* ------------------------------------------------------------------ */
__device__ __forceinline__ unsigned pk(float lo, float hi) {
    unsigned r;
    asm("cvt.rn.bf16x2.f32 %0, %1, %2;" : "=r"(r) : "f"(hi), "f"(lo));
    return r;
}

__device__ __forceinline__ unsigned saddr(const void* p) {
    return (unsigned)__cvta_generic_to_shared(p);
}

__device__ __forceinline__ void cpa16(unsigned dst, const void* src) {
    asm volatile("cp.async.cg.shared.global [%0], [%1], 16;\n"
                 :: "r"(dst), "l"(src));
}

__device__ __forceinline__ void ldsm4(unsigned& r0, unsigned& r1,
                                      unsigned& r2, unsigned& r3, unsigned a) {
    asm volatile("ldmatrix.sync.aligned.m8n8.x4.shared.b16 {%0,%1,%2,%3}, [%4];"
                 : "=r"(r0), "=r"(r1), "=r"(r2), "=r"(r3) : "r"(a));
}

#define CP_COMMIT() asm volatile("cp.async.commit_group;\n")
#define CP_WAIT0()  asm volatile("cp.async.wait_group 0;\n")
#define CP_WAIT1()  asm volatile("cp.async.wait_group 1;\n")
#define CP_WAIT2()  asm volatile("cp.async.wait_group 2;\n")

#define MMA16816(d, a0, a1, a2, a3, b0, b1)                                  \
    asm volatile(                                                            \
        "mma.sync.aligned.m16n8k16.row.col.f32.bf16.bf16.f32 "               \
        "{%0,%1,%2,%3}, {%4,%5,%6,%7}, {%8,%9}, {%0,%1,%2,%3};"              \
        : "+f"(d[0]), "+f"(d[1]), "+f"(d[2]), "+f"(d[3])                     \
        : "r"(a0), "r"(a1), "r"(a2), "r"(a3), "r"(b0), "r"(b1))

/* ------------------------------------------------------------------ */
/* kernel 1: xx = x + sx * time_maa_x, packed bf16 pairs               */
/* ------------------------------------------------------------------ */
__global__ void k_prep_xx(const float* __restrict__ x,
                          const float* __restrict__ state,
                          const float* __restrict__ tmx,
                          const int*   __restrict__ ip)
{
    const int D4 = DIM / 4;
    int idx = blockIdx.x * blockDim.x + threadIdx.x;
    if (idx >= NTOK * D4) return;
    int j   = idx & (D4 - 1);
    int r   = idx / D4;
    int t   = r & (SEQ - 1);
    int b   = r / SEQ;
    int c   = j * 4;
    int i1  = SROWS * ip[0] + 1;

    float4 xc = *(const float4*)(x + (size_t)r * DIM + c);
    float4 xp;
    if (t == 0)
        xp = *(const float4*)(state + ((size_t)b * SROWS + i1) * DIM + c);
    else
        xp = *(const float4*)(x + (size_t)(r - 1) * DIM + c);
    float4 m = *(const float4*)(tmx + c);

    float e0 = xc.x + (xp.x - xc.x) * m.x;
    float e1 = xc.y + (xp.y - xc.y) * m.y;
    float e2 = xc.z + (xp.z - xc.z) * m.z;
    float e3 = xc.w + (xp.w - xc.w) * m.w;

    uint2 o;
    o.x = pk(e0, e1);
    o.y = pk(e2, e3);
    *(uint2*)(g_xx + (size_t)r * D2 + 2 * j) = o;
}

/* ------------------------------------------------------------------ */
/* kernel 2: pack W1^T and W2 into bf16-pair layouts                   */
/* ------------------------------------------------------------------ */
__global__ void k_packw(const float* __restrict__ w1,   /* [DIM,160] */
                        const float* __restrict__ w2)   /* [5,32,DIM] */
{
    int tid = blockIdx.x * blockDim.x + threadIdx.x;
    const int NW1 = RDIM * D2;
    if (tid < NW1) {
        int n = tid / D2;
        int j = tid - n * D2;
        float lo = w1[(size_t)(2 * j)     * RDIM + n];
        float hi = w1[(size_t)(2 * j + 1) * RDIM + n];
        g_w1t[n * D2 + j] = pk(lo, hi);
    } else {
        int q = tid - NW1;
        if (q >= 5 * DIM * 16) return;
        int f   = q / (DIM * 16);
        int rem = q - f * DIM * 16;
        int d   = rem / 16;
        int j   = rem - d * 16;
        float lo = w2[((size_t)(f * 32 + 2 * j))     * DIM + d];
        float hi = w2[((size_t)(f * 32 + 2 * j + 1)) * DIM + d];
        g_w2p[((size_t)f * DIM + d) * 16 + j] = pk(lo, hi);
    }
}

/* ------------------------------------------------------------------ */
/* kernel 3: new_state output                                          */
/* ------------------------------------------------------------------ */
__global__ void k_state(const float* __restrict__ x,
                        const float* __restrict__ state,
                        const int*   __restrict__ ip,
                        float* __restrict__ out_state)
{
    int idx = blockIdx.x * blockDim.x + threadIdx.x;
    if (idx >= BATCH * SROWS * DIM) return;
    int d   = idx & (DIM - 1);
    int row = (idx / DIM) % SROWS;
    int b   = idx / (DIM * SROWS);
    int i1  = SROWS * ip[0] + 1;
    float v = (row == i1) ? x[((size_t)b * SEQ + SEQ - 1) * DIM + d]
                          : state[idx];
    out_state[idx] = v;
}

/* ------------------------------------------------------------------ */
/* kernel 4: GEMM1 split-K  partial = xx @ W1  (K half per CTA)        */
/*   grid 256 (128 m-tiles x 2 K-halves), 8 warps (4m x 2n)            */
/*   3-stage cp.async pipeline, K=64 super-chunks, ldmatrix frags      */
/* ------------------------------------------------------------------ */
#define PC1   32                /* bf16-pairs per chunk (K=64)    */
#define NCHH  16                /* chunks per K-half              */
#define BSTR  36                /* padded smem row stride (words) */
#define STW   ((RDIM + 64) * BSTR)   /* words per stage = 8064    */

__global__ void __launch_bounds__(256) k_gemm1()
{
    extern __shared__ unsigned sm[];   /* 3 stages x 32256 B = 94.5 KB */

    int tid  = threadIdx.x;
    int warp = tid >> 5, lane = tid & 31;
    int gid  = lane >> 2, tig = lane & 3;
    int wm   = warp & 3,  wn  = warp >> 2;
    int mt   = blockIdx.x & 127;       /* m-tile   */
    int kh   = blockIdx.x >> 7;        /* K half   */
    int m0   = mt * 64;
    int c0   = kh * NCHH;

    float acc[10][4];
#pragma unroll
    for (int nt = 0; nt < 10; nt++)
#pragma unroll
        for (int e = 0; e < 4; e++) acc[nt][e] = 0.f;

    /* ldmatrix lane address components (within a stage) */
    int lg = lane >> 3, lr = lane & 7;
    unsigned aOff = ((RDIM + wm * 16 + ((lg & 1) << 3) + lr) * BSTR
                     + ((lg >> 1) << 2)) * 4;
    unsigned bOff = ((wn * 80 + ((lg >> 1) << 3) + lr) * BSTR
                     + ((lg & 1) << 2)) * 4;

    /* stage chunk c into stage s: B rows then A rows (8 segs each) */
#define G1_STAGE(s, c)                                                       \
    do {                                                                     \
        unsigned* Bp = sm + (s) * STW;                                       \
        unsigned* Ap = Bp + RDIM * BSTR;                                     \
        for (int idx = tid; idx < 1792; idx += 256) {                        \
            if (idx < 1280) {                                                \
                int n = idx >> 3, seg = idx & 7;                             \
                cpa16(saddr(&Bp[n * BSTR + seg * 4]),                        \
                      g_w1t + (size_t)n * D2 + (c) * PC1 + seg * 4);         \
            } else {                                                         \
                int a2 = idx - 1280;                                         \
                int row = a2 >> 3, seg = a2 & 7;                             \
                cpa16(saddr(&Ap[row * BSTR + seg * 4]),                      \
                      g_xx + (size_t)(m0 + row) * D2 + (c) * PC1 + seg * 4); \
            }                                                                \
        }                                                                    \
        CP_COMMIT();                                                         \
    } while (0)

    G1_STAGE(0, c0);
    G1_STAGE(1, c0 + 1);

    int s = 0;
    for (int cc = 0; cc < NCHH; cc++) {
        int s2 = s + 2; if (s2 >= 3) s2 -= 3;
        if (cc + 2 < NCHH) {
            G1_STAGE(s2, c0 + cc + 2);
            CP_WAIT2();
        } else if (cc + 1 < NCHH) {
            CP_WAIT1();
        } else {
            CP_WAIT0();
        }
        __syncthreads();                 /* chunk visible to all warps */

        unsigned base = saddr(sm + s * STW);
        unsigned aB = base + aOff;
        unsigned bB = base + bOff;
#pragma unroll
        for (int ks = 0; ks < 4; ks++) {
            unsigned a0, a1, a2, a3;
            ldsm4(a0, a1, a2, a3, aB + ks * 32);
#pragma unroll
            for (int u = 0; u < 5; u++) {
                unsigned b0, b1, b2, b3;
                ldsm4(b0, b1, b2, b3, bB + u * (16 * BSTR * 4) + ks * 32);
                MMA16816(acc[2 * u],     a0, a1, a2, a3, b0, b1);
                MMA16816(acc[2 * u + 1], a0, a1, a2, a3, b2, b3);
            }
        }
        __syncthreads();                 /* stage s free for re-staging */
        s = s + 1; if (s >= 3) s -= 3;
    }

    int rowA = m0 + wm * 16 + gid;
    int rowB = rowA + 8;
    float2* P = g_p1[kh];
#pragma unroll
    for (int nt = 0; nt < 10; nt++) {
        P[(size_t)rowA * R2 + wn * 40 + nt * 4 + tig] =
            make_float2(acc[nt][0], acc[nt][1]);
        P[(size_t)rowB * R2 + wn * 40 + nt * 4 + tig] =
            make_float2(acc[nt][2], acc[nt][3]);
    }
#undef G1_STAGE
}

/* ------------------------------------------------------------------ */
/* kernel 4b: reduce split-K partials, tanh, pack bf16                 */
/*   2 pairs per thread (float4 loads)                                 */
/* ------------------------------------------------------------------ */
__global__ void k_red1()
{
    int idx = blockIdx.x * blockDim.x + threadIdx.x;   /* over NTOK*R2/2 */
    if (idx >= NTOK * R2 / 2) return;
    float4 p0 = *(const float4*)&g_p1[0][(size_t)idx * 2];
    float4 p1 = *(const float4*)&g_p1[1][(size_t)idx * 2];
    uint2 o;
    o.x = pk(tanhf(p0.x + p1.x), tanhf(p0.y + p1.y));
    o.y = pk(tanhf(p0.z + p1.z), tanhf(p0.w + p1.w));
    *(uint2*)&g_xxx[(size_t)idx * 2] = o;
}

/* ------------------------------------------------------------------ */
/* kernel 5: GEMM2 + epilogue                                          */
/*   256 thr, tile 64 tok x 64 d; grid (128, 32); 8 warps (4m x 2n)    */
/*   smem-transposed epilogue -> float4 coalesced streaming stores     */
/* ------------------------------------------------------------------ */
#define G2WS 20     /* w2s row stride (words)  */
#define G2XS 84     /* xs  row stride (words)  */
#define G2ES 72     /* es  row stride (floats) */

__global__ void __launch_bounds__(256) k_gemm2_epi(
    const float* __restrict__ x, const float* __restrict__ state,
    const int* __restrict__ ip,
    const float* __restrict__ mk, const float* __restrict__ mw,
    const float* __restrict__ mv, const float* __restrict__ mr,
    const float* __restrict__ mg,
    float* __restrict__ out)
{
    __shared__ unsigned w2s[5 * 64 * G2WS];    /* 25600 B */
    __shared__ unsigned xs[64 * G2XS];         /* 21504 B */
    float* es = (float*)w2s;                   /* overlay after MMA phase */

    int tid  = threadIdx.x;
    int warp = tid >> 5, lane = tid & 31;
    int gid  = lane >> 2, tig = lane & 3;
    int wm   = warp & 3,  wn  = warp >> 2;
    int m0   = blockIdx.x * 64, d0 = blockIdx.y * 64;

    /* stage w2 tile (5 x 64 cols x 16 pairs) + xxx rows (64 x 80 pairs) */
    for (int idx = tid; idx < 2560; idx += 256) {
        if (idx < 1280) {
            int q = idx >> 2, seg = idx & 3;
            int f = q >> 6, dn = q & 63;
            cpa16(saddr(&w2s[(f * 64 + dn) * G2WS + seg * 4]),
                  g_w2p + ((size_t)f * DIM + d0 + dn) * 16 + seg * 4);
        } else {
            int a = idx - 1280;
            int row = a / 20, seg = a % 20;
            cpa16(saddr(&xs[row * G2XS + seg * 4]),
                  g_xxx + (size_t)(m0 + row) * R2 + seg * 4);
        }
    }
    CP_COMMIT();
    CP_WAIT0();
    __syncthreads();

    float acc[5][4][4];
#pragma unroll
    for (int f = 0; f < 5; f++)
#pragma unroll
        for (int nt = 0; nt < 4; nt++)
#pragma unroll
            for (int e = 0; e < 4; e++) acc[f][nt][e] = 0.f;

    int lg = lane >> 3, lr = lane & 7;
    unsigned aBase = saddr(xs) +
        ((wm * 16 + ((lg & 1) << 3) + lr) * G2XS + ((lg >> 1) << 2)) * 4;
    unsigned bBase = saddr(w2s) +
        ((wn * 32 + ((lg >> 1) << 3) + lr) * G2WS + ((lg & 1) << 2)) * 4;

#pragma unroll
    for (int f = 0; f < 5; f++) {
#pragma unroll
        for (int s = 0; s < 2; s++) {
            unsigned a0, a1, a2, a3;
            ldsm4(a0, a1, a2, a3, aBase + (f * 16 + s * 8) * 4);
#pragma unroll
            for (int u = 0; u < 2; u++) {
                unsigned b0, b1, b2, b3;
                ldsm4(b0, b1, b2, b3,
                      bBase + ((f * 64 + u * 16) * G2WS) * 4 + s * 32);
                MMA16816(acc[f][2 * u],     a0, a1, a2, a3, b0, b1);
                MMA16816(acc[f][2 * u + 1], a0, a1, a2, a3, b2, b3);
            }
        }
    }
    __syncthreads();    /* all smem MMA reads done before es overlay */

    int i1 = SROWS * ip[0] + 1;
    int b  = m0 / SEQ;
    const float* maas[5] = {mk, mw, mv, mr, mg};

#pragma unroll
    for (int f = 0; f < 5; f++) {
        /* scatter this mode's fragments into es */
        int row0 = wm * 16 + gid;
#pragma unroll
        for (int nt = 0; nt < 4; nt++) {
            int col = wn * 32 + nt * 8 + 2 * tig;
            *(float2*)&es[row0 * G2ES + col] =
                make_float2(acc[f][nt][0], acc[f][nt][1]);
            *(float2*)&es[(row0 + 8) * G2ES + col] =
                make_float2(acc[f][nt][2], acc[f][nt][3]);
        }
        __syncthreads();

        const float* maa = maas[f];
#pragma unroll
        for (int p = 0; p < 4; p++) {
            int idx = p * 256 + tid;
            int row = idx >> 4, cq = idx & 15;
            int c   = d0 + cq * 4;
            int r   = m0 + row;
            const float* xrow = x + (size_t)r * DIM;
            int t = r & (SEQ - 1);
            const float* prow = t ? (xrow - DIM)
                                  : (state + ((size_t)b * SROWS + i1) * DIM);
            float4 xc = *(const float4*)(xrow + c);
            float4 xp = *(const float4*)(prow + c);
            float4 mm = *(const float4*)(maa + c);
            float4 ev = *(const float4*)&es[row * G2ES + cq * 4];
            float4 o;
            o.x = xc.x + (xp.x - xc.x) * (mm.x + ev.x);
            o.y = xc.y + (xp.y - xc.y) * (mm.y + ev.y);
            o.z = xc.z + (xp.z - xc.z) * (mm.z + ev.z);
            o.w = xc.w + (xp.w - xc.w) * (mm.w + ev.w);
            __stcs((float4*)(out + ((size_t)r * 5 + f) * DIM + c), o);
        }
        __syncthreads();
    }
}

/* ------------------------------------------------------------------ */
extern "C" void kernel_launch(void* const* d_in, const int* in_sizes, int n_in,
                              void* d_out, int out_size)
{
    const float* x     = (const float*)d_in[0];
    const float* state = (const float*)d_in[1];
    const float* tmx   = (const float*)d_in[2];
    const float* w1    = (const float*)d_in[3];
    const float* w2    = (const float*)d_in[4];
    const float* mk    = (const float*)d_in[5];
    const float* mw    = (const float*)d_in[6];
    const float* mv    = (const float*)d_in[7];
    const float* mr    = (const float*)d_in[8];
    const float* mg    = (const float*)d_in[9];
    const int*   ip    = (const int*)d_in[10];

    float* out       = (float*)d_out;
    float* out_state = out + (size_t)NTOK * 5 * DIM;

    static int smem_set = 0;
    const int g1_smem = 3 * STW * 4;   /* 96768 B */
    if (!smem_set) {
        cudaFuncSetAttribute(k_gemm1,
            cudaFuncAttributeMaxDynamicSharedMemorySize, g1_smem);
        smem_set = 1;
    }

    {   /* kernel 1: prep xx */
        int n = NTOK * (DIM / 4);
        k_prep_xx<<<(n + 255) / 256, 256>>>(x, state, tmx, ip);
    }
    {   /* kernel 2: pack weights */
        int n = RDIM * D2 + 5 * DIM * 16;
        k_packw<<<(n + 255) / 256, 256>>>(w1, w2);
    }
    {   /* kernel 3: new_state */
        int n = BATCH * SROWS * DIM;
        k_state<<<(n + 255) / 256, 256>>>(x, state, ip, out_state);
    }
    /* kernel 4: GEMM1 split-K partials */
    k_gemm1<<<256, 256, g1_smem>>>();
    /* kernel 4b: reduce + tanh + pack */
    {
        int n = NTOK * R2 / 2;
        k_red1<<<(n + 255) / 256, 256>>>();
    }
    /* kernel 5: GEMM2 + epilogue */
    k_gemm2_epi<<<dim3(NTOK / 64, DIM / 64), 256>>>(
        x, state, ip, mk, mw, mv, mr, mg, out);
}

// round 17
// speedup vs baseline: 1.8427x; 1.0138x over previous
#include <cuda_runtime.h>
#include <cuda_bf16.h>

#define BATCH 4
#define SEQ   2048
#define DIM   2048
#define NTOK  (BATCH*SEQ)     /* 8192 */
#define RDIM  160
#define SROWS 66              /* 2 + HEAD_SIZE */
#define D2    (DIM/2)         /* 1024 pairs per row */
#define R2    (RDIM/2)        /* 80 pairs per row  */

/* ------------------------------------------------------------------ */
/* scratch (device globals: no allocation allowed)                     */
/* ------------------------------------------------------------------ */
__device__ unsigned g_w1t[RDIM * D2];           /* bf16x2: W1^T pairs  */
__device__ unsigned g_xxx[(size_t)NTOK * R2];   /* bf16x2: tanh(xx@W1) */
__device__ unsigned g_w2p[5 * DIM * 16];        /* bf16x2: W2 pairs    */
__device__ float2   g_p1[2][(size_t)NTOK * R2]; /* fp32 split-K partials */

/* ------------------------------------------------------------------ */
/* helpers                                                             */
/* ------------------------------------------------------------------ */
__device__ __forceinline__ unsigned pk(float lo, float hi) {
    unsigned r;
    asm("cvt.rn.bf16x2.f32 %0, %1, %2;" : "=r"(r) : "f"(hi), "f"(lo));
    return r;
}

__device__ __forceinline__ unsigned saddr(const void* p) {
    return (unsigned)__cvta_generic_to_shared(p);
}

__device__ __forceinline__ void cpa16(unsigned dst, const void* src) {
    asm volatile("cp.async.cg.shared.global [%0], [%1], 16;\n"
                 :: "r"(dst), "l"(src));
}

__device__ __forceinline__ void ldsm4(unsigned& r0, unsigned& r1,
                                      unsigned& r2, unsigned& r3, unsigned a) {
    asm volatile("ldmatrix.sync.aligned.m8n8.x4.shared.b16 {%0,%1,%2,%3}, [%4];"
                 : "=r"(r0), "=r"(r1), "=r"(r2), "=r"(r3) : "r"(a));
}

#define CP_COMMIT() asm volatile("cp.async.commit_group;\n")
#define CP_WAIT0()  asm volatile("cp.async.wait_group 0;\n")

#define MMA16816(d, a0, a1, a2, a3, b0, b1)                                  \
    asm volatile(                                                            \
        "mma.sync.aligned.m16n8k16.row.col.f32.bf16.bf16.f32 "               \
        "{%0,%1,%2,%3}, {%4,%5,%6,%7}, {%8,%9}, {%0,%1,%2,%3};"              \
        : "+f"(d[0]), "+f"(d[1]), "+f"(d[2]), "+f"(d[3])                     \
        : "r"(a0), "r"(a1), "r"(a2), "r"(a3), "r"(b0), "r"(b1))

/* ------------------------------------------------------------------ */
/* kernel 2: pack W1^T and W2 into bf16-pair layouts                   */
/* ------------------------------------------------------------------ */
__global__ void k_packw(const float* __restrict__ w1,   /* [DIM,160] */
                        const float* __restrict__ w2)   /* [5,32,DIM] */
{
    int tid = blockIdx.x * blockDim.x + threadIdx.x;
    const int NW1 = RDIM * D2;
    if (tid < NW1) {
        int n = tid / D2;
        int j = tid - n * D2;
        float lo = w1[(size_t)(2 * j)     * RDIM + n];
        float hi = w1[(size_t)(2 * j + 1) * RDIM + n];
        g_w1t[n * D2 + j] = pk(lo, hi);
    } else {
        int q = tid - NW1;
        if (q >= 5 * DIM * 16) return;
        int f   = q / (DIM * 16);
        int rem = q - f * DIM * 16;
        int d   = rem / 16;
        int j   = rem - d * 16;
        float lo = w2[((size_t)(f * 32 + 2 * j))     * DIM + d];
        float hi = w2[((size_t)(f * 32 + 2 * j + 1)) * DIM + d];
        g_w2p[((size_t)f * DIM + d) * 16 + j] = pk(lo, hi);
    }
}

/* ------------------------------------------------------------------ */
/* kernel 3: new_state output                                          */
/* ------------------------------------------------------------------ */
__global__ void k_state(const float* __restrict__ x,
                        const float* __restrict__ state,
                        const int*   __restrict__ ip,
                        float* __restrict__ out_state)
{
    int idx = blockIdx.x * blockDim.x + threadIdx.x;
    if (idx >= BATCH * SROWS * DIM) return;
    int d   = idx & (DIM - 1);
    int row = (idx / DIM) % SROWS;
    int b   = idx / (DIM * SROWS);
    int i1  = SROWS * ip[0] + 1;
    float v = (row == i1) ? x[((size_t)b * SEQ + SEQ - 1) * DIM + d]
                          : state[idx];
    out_state[idx] = v;
}

/* ------------------------------------------------------------------ */
/* kernel 4: fused prep + GEMM1 split-K  partial = (x+sx*tmx) @ W1     */
/*   grid 256 (128 m-tiles x 2 K-halves), 8 warps (4m x 2n)            */
/*   2-stage cp.async of raw x tile + W1; in-smem transform -> bf16 A  */
/* ------------------------------------------------------------------ */
#define PC1   32                /* bf16-pairs per chunk (K=64 floats) */
#define NCHH  16                /* chunks per K-half                  */
#define BSTR  36                /* A/B padded row stride (words)      */
#define XSTR1 68                /* x raw row stride (floats)          */
#define STW   ((RDIM + 64) * BSTR + 65 * XSTR1)  /* 12484 words/stage */
#define G1_SMEM (2 * STW * 4 + 1024 * 4)         /* 103968 B          */

__global__ void __launch_bounds__(256, 2) k_gemm1(
    const float* __restrict__ x,
    const float* __restrict__ state,
    const float* __restrict__ tmx,
    const int*   __restrict__ ip)
{
    extern __shared__ unsigned sm[];
    float* tmxs = (float*)(sm + 2 * STW);     /* this half's tmx slice */

    int tid  = threadIdx.x;
    int warp = tid >> 5, lane = tid & 31;
    int gid  = lane >> 2, tig = lane & 3;
    int wm   = warp & 3,  wn  = warp >> 2;
    int mt   = blockIdx.x & 127;       /* m-tile   */
    int kh   = blockIdx.x >> 7;        /* K half   */
    int m0   = mt * 64;
    int c0   = kh * NCHH;
    int b    = m0 / SEQ;
    int i1   = SROWS * ip[0] + 1;

    /* row -1 source: state row i1 at batch starts, else x[m0-1] */
    const float* prow0 = (m0 & (SEQ - 1))
        ? (x + (size_t)(m0 - 1) * DIM)
        : (state + ((size_t)b * SROWS + i1) * DIM);

    float acc[10][4];
#pragma unroll
    for (int nt = 0; nt < 10; nt++)
#pragma unroll
        for (int e = 0; e < 4; e++) acc[nt][e] = 0.f;

    /* ldmatrix lane address components (within a stage) */
    int lg = lane >> 3, lr = lane & 7;
    unsigned aOff = ((RDIM + wm * 16 + ((lg & 1) << 3) + lr) * BSTR
                     + ((lg >> 1) << 2)) * 4;
    unsigned bOff = ((wn * 80 + ((lg >> 1) << 3) + lr) * BSTR
                     + ((lg & 1) << 2)) * 4;

    /* transform indices: thread -> (row 0..63, quad 0..3) */
    int trow = tid >> 2, tq = tid & 3;

    /* stage chunk c (global idx) into stage s: W1 rows + raw x rows */
#define G1_STAGE(s, c)                                                       \
    do {                                                                     \
        unsigned* Bp = sm + (s) * STW;                                       \
        float*    Xp = (float*)(Bp + (RDIM + 64) * BSTR);                    \
        for (int idx = tid; idx < 2320; idx += 256) {                        \
            if (idx < 1280) {                                                \
                int n = idx >> 3, seg = idx & 7;                             \
                cpa16(saddr(&Bp[n * BSTR + seg * 4]),                        \
                      g_w1t + (size_t)n * D2 + (c) * PC1 + seg * 4);         \
            } else {                                                         \
                int xi = idx - 1280;                                         \
                int row = xi >> 4, seg = xi & 15;                            \
                const float* src = (row == 0)                                \
                    ? (prow0 + (c) * 64 + seg * 4)                           \
                    : (x + (size_t)(m0 + row - 1) * DIM + (c) * 64 + seg * 4);\
                cpa16(saddr(&Xp[row * XSTR1 + seg * 4]), src);               \
            }                                                                \
        }                                                                    \
        CP_COMMIT();                                                         \
    } while (0)

    /* tmx slice for this K-half (1024 floats), shares group with stage 0 */
    cpa16(saddr(&tmxs[tid * 4]), tmx + kh * 1024 + tid * 4);
    G1_STAGE(0, c0);

    for (int cc = 0; cc < NCHH; cc++) {
        int s = cc & 1;
        CP_WAIT0();              /* chunk cc (and tmx on cc==0) landed */
        __syncthreads();

        if (cc + 1 < NCHH)
            G1_STAGE(s ^ 1, c0 + cc + 1);   /* overlaps transform + MMA */

        /* transform: A[row][pair] = bf16(x + (xprev - x) * tmx) */
        {
            unsigned* Bp = sm + s * STW;
            unsigned* Ap = Bp + RDIM * BSTR;
            float*    Xp = (float*)(Bp + (RDIM + 64) * BSTR);
            const float4* xc = (const float4*)(Xp + (trow + 1) * XSTR1 + tq * 16);
            const float4* xp = (const float4*)(Xp + trow * XSTR1 + tq * 16);
            const float4* tm = (const float4*)(tmxs + cc * 64 + tq * 16);
            unsigned* Ao = Ap + trow * BSTR + tq * 8;
#pragma unroll
            for (int j = 0; j < 4; j++) {
                float4 a = xc[j], p = xp[j], m = tm[j];
                float e0 = a.x + (p.x - a.x) * m.x;
                float e1 = a.y + (p.y - a.y) * m.y;
                float e2 = a.z + (p.z - a.z) * m.z;
                float e3 = a.w + (p.w - a.w) * m.w;
                uint2 o; o.x = pk(e0, e1); o.y = pk(e2, e3);
                *(uint2*)&Ao[j * 2] = o;
            }
        }
        __syncthreads();         /* A region ready for LDSM */

        unsigned base = saddr(sm + s * STW);
        unsigned aB = base + aOff;
        unsigned bB = base + bOff;
#pragma unroll
        for (int ks = 0; ks < 4; ks++) {
            unsigned a0, a1, a2, a3;
            ldsm4(a0, a1, a2, a3, aB + ks * 32);
#pragma unroll
            for (int u = 0; u < 5; u++) {
                unsigned b0, b1, b2, b3;
                ldsm4(b0, b1, b2, b3, bB + u * (16 * BSTR * 4) + ks * 32);
                MMA16816(acc[2 * u],     a0, a1, a2, a3, b0, b1);
                MMA16816(acc[2 * u + 1], a0, a1, a2, a3, b2, b3);
            }
        }
    }

    int rowA = m0 + wm * 16 + gid;
    int rowB = rowA + 8;
    float2* P = g_p1[kh];
#pragma unroll
    for (int nt = 0; nt < 10; nt++) {
        P[(size_t)rowA * R2 + wn * 40 + nt * 4 + tig] =
            make_float2(acc[nt][0], acc[nt][1]);
        P[(size_t)rowB * R2 + wn * 40 + nt * 4 + tig] =
            make_float2(acc[nt][2], acc[nt][3]);
    }
#undef G1_STAGE
}

/* ------------------------------------------------------------------ */
/* kernel 4b: reduce split-K partials, tanh, pack bf16                 */
/* ------------------------------------------------------------------ */
__global__ void k_red1()
{
    int idx = blockIdx.x * blockDim.x + threadIdx.x;   /* over NTOK*R2/2 */
    if (idx >= NTOK * R2 / 2) return;
    float4 p0 = *(const float4*)&g_p1[0][(size_t)idx * 2];
    float4 p1 = *(const float4*)&g_p1[1][(size_t)idx * 2];
    uint2 o;
    o.x = pk(tanhf(p0.x + p1.x), tanhf(p0.y + p1.y));
    o.y = pk(tanhf(p0.z + p1.z), tanhf(p0.w + p1.w));
    *(uint2*)&g_xxx[(size_t)idx * 2] = o;
}

/* ------------------------------------------------------------------ */
/* kernel 5: GEMM2 + epilogue                                          */
/*   256 thr, tile 64 tok x 64 d; grid (128, 32); 8 warps (4m x 2n)    */
/*   smem-transposed epilogue -> float4 coalesced streaming stores     */
/* ------------------------------------------------------------------ */
#define G2WS 20     /* w2s row stride (words)  */
#define G2XS 84     /* xs  row stride (words)  */
#define G2ES 72     /* es  row stride (floats) */

__global__ void __launch_bounds__(256) k_gemm2_epi(
    const float* __restrict__ x, const float* __restrict__ state,
    const int* __restrict__ ip,
    const float* __restrict__ mk, const float* __restrict__ mw,
    const float* __restrict__ mv, const float* __restrict__ mr,
    const float* __restrict__ mg,
    float* __restrict__ out)
{
    __shared__ unsigned w2s[5 * 64 * G2WS];    /* 25600 B */
    __shared__ unsigned xs[64 * G2XS];         /* 21504 B */
    float* es = (float*)w2s;                   /* overlay after MMA phase */

    int tid  = threadIdx.x;
    int warp = tid >> 5, lane = tid & 31;
    int gid  = lane >> 2, tig = lane & 3;
    int wm   = warp & 3,  wn  = warp >> 2;
    int m0   = blockIdx.x * 64, d0 = blockIdx.y * 64;

    /* stage w2 tile (5 x 64 cols x 16 pairs) + xxx rows (64 x 80 pairs) */
    for (int idx = tid; idx < 2560; idx += 256) {
        if (idx < 1280) {
            int q = idx >> 2, seg = idx & 3;
            int f = q >> 6, dn = q & 63;
            cpa16(saddr(&w2s[(f * 64 + dn) * G2WS + seg * 4]),
                  g_w2p + ((size_t)f * DIM + d0 + dn) * 16 + seg * 4);
        } else {
            int a = idx - 1280;
            int row = a / 20, seg = a % 20;
            cpa16(saddr(&xs[row * G2XS + seg * 4]),
                  g_xxx + (size_t)(m0 + row) * R2 + seg * 4);
        }
    }
    CP_COMMIT();
    CP_WAIT0();
    __syncthreads();

    float acc[5][4][4];
#pragma unroll
    for (int f = 0; f < 5; f++)
#pragma unroll
        for (int nt = 0; nt < 4; nt++)
#pragma unroll
            for (int e = 0; e < 4; e++) acc[f][nt][e] = 0.f;

    int lg = lane >> 3, lr = lane & 7;
    unsigned aBase = saddr(xs) +
        ((wm * 16 + ((lg & 1) << 3) + lr) * G2XS + ((lg >> 1) << 2)) * 4;
    unsigned bBase = saddr(w2s) +
        ((wn * 32 + ((lg >> 1) << 3) + lr) * G2WS + ((lg & 1) << 2)) * 4;

#pragma unroll
    for (int f = 0; f < 5; f++) {
#pragma unroll
        for (int s = 0; s < 2; s++) {
            unsigned a0, a1, a2, a3;
            ldsm4(a0, a1, a2, a3, aBase + (f * 16 + s * 8) * 4);
#pragma unroll
            for (int u = 0; u < 2; u++) {
                unsigned b0, b1, b2, b3;
                ldsm4(b0, b1, b2, b3,
                      bBase + ((f * 64 + u * 16) * G2WS) * 4 + s * 32);
                MMA16816(acc[f][2 * u],     a0, a1, a2, a3, b0, b1);
                MMA16816(acc[f][2 * u + 1], a0, a1, a2, a3, b2, b3);
            }
        }
    }
    __syncthreads();    /* all smem MMA reads done before es overlay */

    int i1 = SROWS * ip[0] + 1;
    int b  = m0 / SEQ;
    const float* maas[5] = {mk, mw, mv, mr, mg};

#pragma unroll
    for (int f = 0; f < 5; f++) {
        /* scatter this mode's fragments into es */
        int row0 = wm * 16 + gid;
#pragma unroll
        for (int nt = 0; nt < 4; nt++) {
            int col = wn * 32 + nt * 8 + 2 * tig;
            *(float2*)&es[row0 * G2ES + col] =
                make_float2(acc[f][nt][0], acc[f][nt][1]);
            *(float2*)&es[(row0 + 8) * G2ES + col] =
                make_float2(acc[f][nt][2], acc[f][nt][3]);
        }
        __syncthreads();

        const float* maa = maas[f];
#pragma unroll
        for (int p = 0; p < 4; p++) {
            int idx = p * 256 + tid;
            int row = idx >> 4, cq = idx & 15;
            int c   = d0 + cq * 4;
            int r   = m0 + row;
            const float* xrow = x + (size_t)r * DIM;
            int t = r & (SEQ - 1);
            const float* prow = t ? (xrow - DIM)
                                  : (state + ((size_t)b * SROWS + i1) * DIM);
            float4 xc = *(const float4*)(xrow + c);
            float4 xp = *(const float4*)(prow + c);
            float4 mm = *(const float4*)(maa + c);
            float4 ev = *(const float4*)&es[row * G2ES + cq * 4];
            float4 o;
            o.x = xc.x + (xp.x - xc.x) * (mm.x + ev.x);
            o.y = xc.y + (xp.y - xc.y) * (mm.y + ev.y);
            o.z = xc.z + (xp.z - xc.z) * (mm.z + ev.z);
            o.w = xc.w + (xp.w - xc.w) * (mm.w + ev.w);
            __stcs((float4*)(out + ((size_t)r * 5 + f) * DIM + c), o);
        }
        __syncthreads();
    }
}

/* ------------------------------------------------------------------ */
extern "C" void kernel_launch(void* const* d_in, const int* in_sizes, int n_in,
                              void* d_out, int out_size)
{
    const float* x     = (const float*)d_in[0];
    const float* state = (const float*)d_in[1];
    const float* tmx   = (const float*)d_in[2];
    const float* w1    = (const float*)d_in[3];
    const float* w2    = (const float*)d_in[4];
    const float* mk    = (const float*)d_in[5];
    const float* mw    = (const float*)d_in[6];
    const float* mv    = (const float*)d_in[7];
    const float* mr    = (const float*)d_in[8];
    const float* mg    = (const float*)d_in[9];
    const int*   ip    = (const int*)d_in[10];

    float* out       = (float*)d_out;
    float* out_state = out + (size_t)NTOK * 5 * DIM;

    static int smem_set = 0;
    if (!smem_set) {
        cudaFuncSetAttribute(k_gemm1,
            cudaFuncAttributeMaxDynamicSharedMemorySize, G1_SMEM);
        smem_set = 1;
    }

    {   /* pack weights */
        int n = RDIM * D2 + 5 * DIM * 16;
        k_packw<<<(n + 255) / 256, 256>>>(w1, w2);
    }
    {   /* new_state */
        int n = BATCH * SROWS * DIM;
        k_state<<<(n + 255) / 256, 256>>>(x, state, ip, out_state);
    }
    /* fused prep + GEMM1 split-K partials */
    k_gemm1<<<256, 256, G1_SMEM>>>(x, state, tmx, ip);
    /* reduce + tanh + pack */
    {
        int n = NTOK * R2 / 2;
        k_red1<<<(n + 255) / 256, 256>>>();
    }
    /* GEMM2 + epilogue */
    k_gemm2_epi<<<dim3(NTOK / 64, DIM / 64), 256>>>(
        x, state, ip, mk, mw, mv, mr, mg, out);
}